// round 10
// baseline (speedup 1.0000x reference)
#include <cuda_runtime.h>
#include <cuda_fp16.h>
#include <cstdint>

#define B_   32
#define S_   4096
#define T_   8192
#define DIN  128
#define DT   256
#define M_   (B_ * T_)        // 262144
#define TILE_M 128
#define NBLK  (M_ / TILE_M)   // 2048
#define NTHR  512

// ---------------- device-global tables (no runtime allocation) -------------
__device__ float    g_slens[B_];
__device__ float    g_w[4];
__device__ uint16_t g_wh[DT * DT];      // W fp16 (rounded), [k][n] row-major
__device__ uint32_t g_peh[T_ * 64];     // pos_emb packed fp16x2, [t][pair]

// ---------------- smem layout (swizzled, pitch 512) ------------------------
#define OFF_A    0              // 128 rows x 512 B (fp16: 256 cols)
#define OFF_B    65536          // 256 k-rows x 512 B = 128 KB (ALL of W)
#define SMEM_TOTAL (OFF_B + 131072)     // 196608 -> 1 CTA/SM, 16 warps
// epilogue overlays (B region is dead after the post-mainloop barrier):
#define OFF_PS   OFF_B
#define OFF_PS2  (OFF_B + 2048)

// ---------------- asm helpers ----------------------------------------------
__device__ __forceinline__ uint32_t smem_u32(const void* p) {
    uint32_t a;
    asm("{ .reg .u64 t; cvta.to.shared.u64 t, %1; cvt.u32.u64 %0, t; }" : "=r"(a) : "l"(p));
    return a;
}
#define CP_ASYNC16(dst, src) \
    asm volatile("cp.async.cg.shared.global [%0], [%1], 16;" :: "r"(dst), "l"(src))
#define CP_COMMIT() asm volatile("cp.async.commit_group;" ::: "memory")
#define CP_WAIT0()  asm volatile("cp.async.wait_group 0;" ::: "memory")

#define LDSM4(r, addr) \
    asm volatile("ldmatrix.sync.aligned.m8n8.x4.shared.b16 {%0,%1,%2,%3}, [%4];" \
        : "=r"((r)[0]), "=r"((r)[1]), "=r"((r)[2]), "=r"((r)[3]) : "r"(addr))
#define LDSM4T(r, addr) \
    asm volatile("ldmatrix.sync.aligned.m8n8.x4.trans.shared.b16 {%0,%1,%2,%3}, [%4];" \
        : "=r"((r)[0]), "=r"((r)[1]), "=r"((r)[2]), "=r"((r)[3]) : "r"(addr))

// NOTE: not volatile -> ptxas is free to schedule/pipeline MMAs.
__device__ __forceinline__ void mma_f16(float* c, const uint32_t* a, const uint32_t* b) {
    asm("mma.sync.aligned.m16n8k16.row.col.f32.f16.f16.f32 "
        "{%0,%1,%2,%3}, {%4,%5,%6,%7}, {%8,%9}, {%0,%1,%2,%3};"
        : "+f"(c[0]), "+f"(c[1]), "+f"(c[2]), "+f"(c[3])
        : "r"(a[0]), "r"(a[1]), "r"(a[2]), "r"(a[3]), "r"(b[0]), "r"(b[1]));
}

__device__ __forceinline__ uint32_t h2u(__half2 h) {
    uint32_t u; *(__half2*)&u = h; return u;
}

__device__ __forceinline__ float gelu_exact(float x) {
    return 0.5f * x * (1.0f + erff(x * 0.70710678118654752440f));
}

// ---------------- kernel 1: s_lens + neighbor softmax ----------------------
__global__ void k_prep(const float* __restrict__ s_mask, const float* __restrict__ nw) {
    int tid = threadIdx.x, w = tid >> 5, lane = tid & 31;
    const float* row = s_mask + (size_t)w * S_;
    float s = 0.f;
    for (int i = lane; i < S_; i += 32) s += row[i];
    #pragma unroll
    for (int o = 16; o; o >>= 1) s += __shfl_xor_sync(0xFFFFFFFFu, s, o);
    if (lane == 0) g_slens[w] = s;
    if (tid == 0) {
        float a = nw[0], b = nw[1], c = nw[2];
        float m = fmaxf(a, fmaxf(b, c));
        float ea = expf(a - m), eb = expf(b - m), ec = expf(c - m);
        float inv = 1.f / (ea + eb + ec);
        g_w[0] = ea * inv; g_w[1] = eb * inv; g_w[2] = ec * inv;
    }
}

// ---------------- kernel 2: pos_emb -> packed fp16x2 [t][64] ---------------
__global__ void k_posemb(const float* __restrict__ w1, const float* __restrict__ b1,
                         const float* __restrict__ w2, const float* __restrict__ b2) {
    __shared__ float h[64];
    int t = blockIdx.x, tid = threadIdx.x;   // 128 threads
    float pos = (float)t * (1.0f / (float)(T_ - 1));
    if (tid < 64) h[tid] = gelu_exact(pos * w1[tid] + b1[tid]);
    __syncthreads();
    float acc = b2[tid];
    #pragma unroll 16
    for (int j = 0; j < 64; j++) acc = fmaf(h[j], w2[j * DIN + tid], acc);
    float x1 = __shfl_down_sync(0xFFFFFFFFu, acc, 1);
    if ((tid & 1) == 0)
        g_peh[t * 64 + (tid >> 1)] = h2u(__floats2half2_rn(acc, x1));
}

// ---------------- kernel 3: W -> fp16 (rounded) [k][n] ---------------------
__global__ void k_wsplit(const float* __restrict__ W) {
    int idx = blockIdx.x * 256 + threadIdx.x;   // 65536
    __half h = __float2half_rn(W[idx]);
    g_wh[idx] = *(uint16_t*)&h;
}

// ---------------- kernel 4: fused gather + fp16 GEMM + epilogue ------------
__global__ void __launch_bounds__(NTHR, 1)
k_main(const float* __restrict__ emb, const float* __restrict__ s_mask,
       const float* __restrict__ tmask,
       const float* __restrict__ bias, const float* __restrict__ lng,
       const float* __restrict__ lnb, float* __restrict__ out) {
    extern __shared__ char smem[];
    uint32_t sb = smem_u32(smem);
    int tid = threadIdx.x, wid = tid >> 5, lane = tid & 31;
    int wm = wid >> 2;        // 0..3 : M quarter (32 rows)
    int wn = wid & 3;         // 0..3 : N quarter (64 cols)
    int m0 = blockIdx.x * TILE_M;
    int t0 = m0 & (T_ - 1);   // all 128 rows share batch b (T divisible by 128)
    int b  = m0 >> 13;

    // early exit: t_mask is a prefix mask -> whole block exactly zero.
    if (tmask[m0] == 0.f) {
        float4 z = make_float4(0.f, 0.f, 0.f, 0.f);
        float4* o4 = (float4*)(out + (size_t)m0 * DT);
        #pragma unroll
        for (int i = 0; i < 16; i++) o4[tid + NTHR * i] = z;   // 128x64 float4
        return;
    }

    // ---- load ALL of B (W fp16, 128 KB) once, swizzled --------------------
    {
        const char* src0 = (const char*)g_wh;
        #pragma unroll
        for (int i = 0; i < 16; i++) {
            int f = tid + NTHR * i;            // 0..8191
            int r = f >> 5;                    // k row (0..255)
            int c = f & 31;                    // 16B segment
            CP_ASYNC16(sb + OFF_B + r * 512 + ((c ^ (r & 7)) << 4),
                       src0 + (size_t)r * 512 + c * 16);
        }
        CP_COMMIT();
    }

    // ---- produce A tile (128 x 256) as fp16, swizzled (8 rows/warp) -------
    {
        float slen = g_slens[b];
        float wv0 = g_w[0], wv1 = g_w[1], wv2 = g_w[2];
        const float* mrow = s_mask + (size_t)b * S_;
        int   ip[8], ic[8], in_[8];
        float w0a[8], w1a[8], w2a[8];
        #pragma unroll
        for (int i = 0; i < 8; i++) {
            int t = t0 + wid * 8 + i;
            float pos = (float)t * (1.0f / (float)(T_ - 1));
            float sp  = pos * (slen - 1.0f);
            int curr = (int)sp;
            ip[i] = max(curr - 1, 0);
            ic[i] = curr;
            in_[i] = min(curr + 1, S_ - 1);
        }
        #pragma unroll
        for (int i = 0; i < 8; i++) {
            w0a[i] = wv0 * mrow[ip[i]];
            w1a[i] = wv1 * mrow[ic[i]];
            w2a[i] = wv2 * mrow[in_[i]];
        }
        #pragma unroll 2
        for (int i = 0; i < 8; i++) {
            int row = wid * 8 + i;
            int t = t0 + row;
            const float4* ep = (const float4*)(emb + ((size_t)b * S_ + ip[i]) * DIN);
            const float4* ec = (const float4*)(emb + ((size_t)b * S_ + ic[i]) * DIN);
            const float4* en = (const float4*)(emb + ((size_t)b * S_ + in_[i]) * DIN);
            float4 vp = ep[lane], vc = ec[lane], vn = en[lane];
            float w0 = w0a[i], w1 = w1a[i], w2 = w2a[i];
            float v0 = w0 * vp.x + w1 * vc.x + w2 * vn.x;
            float v1 = w0 * vp.y + w1 * vc.y + w2 * vn.y;
            float v2 = w0 * vp.z + w1 * vc.z + w2 * vn.z;
            float v3 = w0 * vp.w + w1 * vc.w + w2 * vn.w;
            __half2 hh0 = __floats2half2_rn(v0, v1);
            __half2 hh1 = __floats2half2_rn(v2, v3);
            uint32_t rbase = row * 512;
            uint32_t rxor  = (row & 7) << 4;
            uint32_t o1 = rbase + ((8 * lane) ^ rxor);
            *(uint2*)(smem + OFF_A + o1) = make_uint2(h2u(hh0), h2u(hh1));
            uint2 peh = *(const uint2*)(g_peh + (size_t)t * 64 + 2 * lane);
            uint32_t o2 = rbase + ((256 + 8 * lane) ^ rxor);
            *(uint2*)(smem + OFF_A + o2) = peh;
        }
    }

    // ---- ldmatrix lane addressing ----
    int xr = (lane & 7) + ((lane >> 3) & 1) * 8;   // 0..15
    int xg = lane >> 4;                            // 0..1
    int a_row = wm * 32 + xr;
    uint32_t a_base = sb + OFF_A + a_row * 512;
    uint32_t a_xor  = ((a_row & 7) << 4) ^ (xg * 16);
    uint32_t b_base = sb + OFF_B + xr * 512;
    uint32_t b_xor  = (xr & 7) << 4;
    int b_col = wn * 128 + xg * 16;
    uint32_t co[4];
    #pragma unroll
    for (int p = 0; p < 4; p++) co[p] = ((uint32_t)(b_col + p * 32) ^ b_xor);

    float acc[2][8][4];
    #pragma unroll
    for (int mt = 0; mt < 2; mt++)
        #pragma unroll
        for (int nt = 0; nt < 8; nt++)
            #pragma unroll
            for (int c = 0; c < 4; c++) acc[mt][nt][c] = 0.f;

    CP_WAIT0();
    __syncthreads();   // A + B both ready; mainloop is barrier-free

    // ---- mainloop: 16 k-steps, fully unrolled, no barriers ----------------
    #pragma unroll
    for (int ks = 0; ks < 16; ks++) {
        uint32_t aoff = ((uint32_t)(ks * 32)) ^ a_xor;
        uint32_t A0[4], A1[4];
        LDSM4(A0, a_base + aoff);
        LDSM4(A1, a_base + 16 * 512 + aoff);
        uint32_t bk = b_base + ks * 16 * 512;
        #pragma unroll
        for (int p = 0; p < 4; p++) {
            uint32_t Bf[4];
            LDSM4T(Bf, bk + co[p]);
            mma_f16(acc[0][2 * p],     A0, &Bf[0]);
            mma_f16(acc[0][2 * p + 1], A0, &Bf[2]);
            mma_f16(acc[1][2 * p],     A1, &Bf[0]);
            mma_f16(acc[1][2 * p + 1], A1, &Bf[2]);
        }
    }
    __syncthreads();   // B region dead -> LN partial overlay becomes valid

    // ---- epilogue: gelu + layernorm + mask (params straight from gmem) ----
    float* ps   = (float*)(smem + OFF_PS);
    float* ps2  = (float*)(smem + OFF_PS2);

    float2 bia[8], gg[8], be[8];
    #pragma unroll
    for (int nt = 0; nt < 8; nt++) {
        int c = wn * 64 + nt * 8 + 2 * (lane & 3);
        bia[nt] = *(const float2*)&bias[c];
        gg[nt]  = *(const float2*)&lng[c];
        be[nt]  = *(const float2*)&lnb[c];
    }

    #pragma unroll
    for (int mt = 0; mt < 2; mt++) {
        float sA = 0.f, s2A = 0.f, sB = 0.f, s2B = 0.f;
        #pragma unroll
        for (int nt = 0; nt < 8; nt++) {
            float v0 = gelu_exact(acc[mt][nt][0] + bia[nt].x);
            float v1 = gelu_exact(acc[mt][nt][1] + bia[nt].y);
            float v2 = gelu_exact(acc[mt][nt][2] + bia[nt].x);
            float v3 = gelu_exact(acc[mt][nt][3] + bia[nt].y);
            acc[mt][nt][0] = v0; acc[mt][nt][1] = v1;
            acc[mt][nt][2] = v2; acc[mt][nt][3] = v3;
            sA += v0 + v1; s2A += v0 * v0 + v1 * v1;
            sB += v2 + v3; s2B += v2 * v2 + v3 * v3;
        }
        #pragma unroll
        for (int o = 1; o <= 2; o <<= 1) {
            sA  += __shfl_xor_sync(0xFFFFFFFFu, sA,  o);
            s2A += __shfl_xor_sync(0xFFFFFFFFu, s2A, o);
            sB  += __shfl_xor_sync(0xFFFFFFFFu, sB,  o);
            s2B += __shfl_xor_sync(0xFFFFFFFFu, s2B, o);
        }
        if ((lane & 3) == 0) {
            int rA = wm * 32 + mt * 16 + (lane >> 2);
            ps[rA * 4 + wn]  = sA;  ps2[rA * 4 + wn]  = s2A;
            ps[(rA + 8) * 4 + wn] = sB; ps2[(rA + 8) * 4 + wn] = s2B;
        }
    }
    __syncthreads();

    #pragma unroll
    for (int mt = 0; mt < 2; mt++) {
        int rA = wm * 32 + mt * 16 + (lane >> 2);
        int rB = rA + 8;
        float tsA  = ps[rA * 4] + ps[rA * 4 + 1] + ps[rA * 4 + 2] + ps[rA * 4 + 3];
        float ts2A = ps2[rA * 4] + ps2[rA * 4 + 1] + ps2[rA * 4 + 2] + ps2[rA * 4 + 3];
        float tsB  = ps[rB * 4] + ps[rB * 4 + 1] + ps[rB * 4 + 2] + ps[rB * 4 + 3];
        float ts2B = ps2[rB * 4] + ps2[rB * 4 + 1] + ps2[rB * 4 + 2] + ps2[rB * 4 + 3];
        float muA = tsA * (1.f / 256.f);
        float muB = tsB * (1.f / 256.f);
        float invA = rsqrtf(ts2A * (1.f / 256.f) - muA * muA + 1e-5f);
        float invB = rsqrtf(ts2B * (1.f / 256.f) - muB * muB + 1e-5f);
        float mkA = tmask[m0 + rA];
        float mkB = tmask[m0 + rB];
        #pragma unroll
        for (int nt = 0; nt < 8; nt++) {
            int c = wn * 64 + nt * 8 + 2 * (lane & 3);
            float2 o1, o2;
            o1.x = ((acc[mt][nt][0] - muA) * invA * gg[nt].x + be[nt].x) * mkA;
            o1.y = ((acc[mt][nt][1] - muA) * invA * gg[nt].y + be[nt].y) * mkA;
            o2.x = ((acc[mt][nt][2] - muB) * invB * gg[nt].x + be[nt].x) * mkB;
            o2.y = ((acc[mt][nt][3] - muB) * invB * gg[nt].y + be[nt].y) * mkB;
            *(float2*)(out + (size_t)(m0 + rA) * DT + c) = o1;
            *(float2*)(out + (size_t)(m0 + rB) * DT + c) = o2;
        }
    }
}

// ---------------- launch ---------------------------------------------------
extern "C" void kernel_launch(void* const* d_in, const int* in_sizes, int n_in,
                              void* d_out, int out_size) {
    const float* student_emb = (const float*)d_in[0];
    const float* s_mask      = (const float*)d_in[1];
    const float* t_mask      = (const float*)d_in[2];
    int p = (in_sizes[3] == 64) ? 3 : 4;
    const float* pe_w1 = (const float*)d_in[p + 0];
    const float* pe_b1 = (const float*)d_in[p + 1];
    const float* pe_w2 = (const float*)d_in[p + 2];
    const float* pe_b2 = (const float*)d_in[p + 3];
    const float* pt_w  = (const float*)d_in[p + 4];
    const float* pt_b  = (const float*)d_in[p + 5];
    const float* ln_g  = (const float*)d_in[p + 6];
    const float* ln_b  = (const float*)d_in[p + 7];
    const float* nw    = (const float*)d_in[p + 8];
    float* out = (float*)d_out;

    cudaFuncSetAttribute(k_main, cudaFuncAttributeMaxDynamicSharedMemorySize, SMEM_TOTAL);

    k_prep<<<1, 1024>>>(s_mask, nw);
    k_posemb<<<T_, 128>>>(pe_w1, pe_b1, pe_w2, pe_b2);
    k_wsplit<<<DT * DT / 256, 256>>>(pt_w);
    k_main<<<NBLK, NTHR, SMEM_TOTAL>>>(student_emb, s_mask, t_mask,
                                       pt_b, ln_g, ln_b, out);
}

// round 11
// speedup vs baseline: 1.1175x; 1.1175x over previous
#include <cuda_runtime.h>
#include <cuda_fp16.h>
#include <cstdint>

#define B_   32
#define S_   4096
#define T_   8192
#define DIN  128
#define DT   256
#define M_   (B_ * T_)        // 262144
#define TILE_M 64
#define NBLK  (M_ / TILE_M)   // 4096

// ---------------- device-global tables (no runtime allocation) -------------
__device__ float    g_slens[B_];
__device__ float    g_w[4];
__device__ uint16_t g_wh[DT * DT];      // W fp16 (rounded), [k][n] row-major
__device__ uint32_t g_peh[T_ * 64];     // pos_emb packed fp16x2, [t][pair] (256B/row)

// ---------------- smem layout (swizzled, pitch 512) ------------------------
#define OFF_A    0              // 64 rows x 512 B (fp16: 256 cols)
#define OFF_B0   32768
#define B_STAGE  32768          // 64 k-rows x 512 B (one K64 chunk)
#define SMEM_TOTAL (OFF_B0 + 2 * B_STAGE)   // 98304 -> 2 CTAs/SM
// epilogue overlays (valid after final mainloop barrier; pipeline drained):
#define OFF_PS   OFF_B0
#define OFF_PS2  (OFF_B0 + 1024)

// ---------------- asm helpers ----------------------------------------------
__device__ __forceinline__ uint32_t smem_u32(const void* p) {
    uint32_t a;
    asm("{ .reg .u64 t; cvta.to.shared.u64 t, %1; cvt.u32.u64 %0, t; }" : "=r"(a) : "l"(p));
    return a;
}
#define CP_ASYNC16(dst, src) \
    asm volatile("cp.async.cg.shared.global [%0], [%1], 16;" :: "r"(dst), "l"(src))
#define CP_COMMIT() asm volatile("cp.async.commit_group;" ::: "memory")
#define CP_WAIT0()  asm volatile("cp.async.wait_group 0;" ::: "memory")

#define LDSM4(r, addr) \
    asm volatile("ldmatrix.sync.aligned.m8n8.x4.shared.b16 {%0,%1,%2,%3}, [%4];" \
        : "=r"((r)[0]), "=r"((r)[1]), "=r"((r)[2]), "=r"((r)[3]) : "r"(addr))
#define LDSM4T(r, addr) \
    asm volatile("ldmatrix.sync.aligned.m8n8.x4.trans.shared.b16 {%0,%1,%2,%3}, [%4];" \
        : "=r"((r)[0]), "=r"((r)[1]), "=r"((r)[2]), "=r"((r)[3]) : "r"(addr))

// NOTE: not volatile -> ptxas is free to schedule/pipeline MMAs.
__device__ __forceinline__ void mma_f16(float* c, const uint32_t* a, const uint32_t* b) {
    asm("mma.sync.aligned.m16n8k16.row.col.f32.f16.f16.f32 "
        "{%0,%1,%2,%3}, {%4,%5,%6,%7}, {%8,%9}, {%0,%1,%2,%3};"
        : "+f"(c[0]), "+f"(c[1]), "+f"(c[2]), "+f"(c[3])
        : "r"(a[0]), "r"(a[1]), "r"(a[2]), "r"(a[3]), "r"(b[0]), "r"(b[1]));
}

__device__ __forceinline__ uint32_t h2u(__half2 h) {
    uint32_t u; *(__half2*)&u = h; return u;
}

__device__ __forceinline__ float gelu_exact(float x) {
    return 0.5f * x * (1.0f + erff(x * 0.70710678118654752440f));
}

// ---------------- kernel 1: s_lens + neighbor softmax ----------------------
__global__ void k_prep(const float* __restrict__ s_mask, const float* __restrict__ nw) {
    int tid = threadIdx.x, w = tid >> 5, lane = tid & 31;
    const float* row = s_mask + (size_t)w * S_;
    float s = 0.f;
    for (int i = lane; i < S_; i += 32) s += row[i];
    #pragma unroll
    for (int o = 16; o; o >>= 1) s += __shfl_xor_sync(0xFFFFFFFFu, s, o);
    if (lane == 0) g_slens[w] = s;
    if (tid == 0) {
        float a = nw[0], b = nw[1], c = nw[2];
        float m = fmaxf(a, fmaxf(b, c));
        float ea = expf(a - m), eb = expf(b - m), ec = expf(c - m);
        float inv = 1.f / (ea + eb + ec);
        g_w[0] = ea * inv; g_w[1] = eb * inv; g_w[2] = ec * inv;
    }
}

// ---------------- kernel 2: pos_emb -> packed fp16x2 [t][64] ---------------
__global__ void k_posemb(const float* __restrict__ w1, const float* __restrict__ b1,
                         const float* __restrict__ w2, const float* __restrict__ b2) {
    __shared__ float h[64];
    int t = blockIdx.x, tid = threadIdx.x;   // 128 threads
    float pos = (float)t * (1.0f / (float)(T_ - 1));
    if (tid < 64) h[tid] = gelu_exact(pos * w1[tid] + b1[tid]);
    __syncthreads();
    float acc = b2[tid];
    #pragma unroll 16
    for (int j = 0; j < 64; j++) acc = fmaf(h[j], w2[j * DIN + tid], acc);
    float x1 = __shfl_down_sync(0xFFFFFFFFu, acc, 1);
    if ((tid & 1) == 0)
        g_peh[t * 64 + (tid >> 1)] = h2u(__floats2half2_rn(acc, x1));
}

// ---------------- kernel 3: W -> fp16 (rounded) [k][n] ---------------------
__global__ void k_wsplit(const float* __restrict__ W) {
    int idx = blockIdx.x * 256 + threadIdx.x;   // 65536
    __half h = __float2half_rn(W[idx]);
    g_wh[idx] = *(uint16_t*)&h;
}

// ---------------- B chunk loader: K=64, swizzled, cp.async (32KB) ----------
__device__ __forceinline__ void load_B_chunk(uint32_t sb, int stage, int chunk, int tid) {
    uint32_t dst = sb + OFF_B0 + stage * B_STAGE;
    const char* src0 = (const char*)(g_wh + chunk * 64 * DT);
    #pragma unroll
    for (int i = 0; i < 8; i++) {
        int f = tid + 256 * i;             // 0..2047
        int r = f >> 5;                    // K row within chunk (0..63)
        int c = f & 31;                    // 16B segment
        CP_ASYNC16(dst + r * 512 + ((c ^ (r & 7)) << 4), src0 + (size_t)r * 512 + c * 16);
    }
}

// ---------------- kernel 4: fused gather + fp16 GEMM + epilogue ------------
__global__ void __launch_bounds__(256, 2)
k_main(const float* __restrict__ emb, const float* __restrict__ s_mask,
       const float* __restrict__ tmask,
       const float* __restrict__ bias, const float* __restrict__ lng,
       const float* __restrict__ lnb, float* __restrict__ out) {
    extern __shared__ char smem[];
    uint32_t sb = smem_u32(smem);
    int tid = threadIdx.x, wid = tid >> 5, lane = tid & 31;
    int wm = wid >> 2;        // 0..1 : M half (32 rows)
    int wn = wid & 3;         // 0..3 : N quarter (64 cols)
    int m0 = blockIdx.x * TILE_M;
    int t0 = m0 & (T_ - 1);   // all 64 rows share batch b
    int b  = m0 >> 13;

    // early exit: t_mask is a prefix mask -> whole block exactly zero.
    if (tmask[m0] == 0.f) {
        float4 z = make_float4(0.f, 0.f, 0.f, 0.f);
        float4* o4 = (float4*)(out + (size_t)m0 * DT);
        #pragma unroll
        for (int i = 0; i < 16; i++) o4[tid + 256 * i] = z;
        return;
    }

    // prefetch B chunk 0 + pos_emb half of A (cp.async, group 0)
    load_B_chunk(sb, 0, 0, tid);
    {
        // A rows: cols 128..255 = 256 contiguous bytes from g_peh[t][*]
        #pragma unroll
        for (int i = 0; i < 4; i++) {
            int f = tid + 256 * i;         // 0..1023
            int row = f >> 4;              // 0..63
            int seg = f & 15;              // 16B segment within 256B
            uint32_t byte = (uint32_t)(256 + seg * 16) ^ ((row & 7) << 4);
            CP_ASYNC16(sb + OFF_A + row * 512 + byte,
                       (const char*)(g_peh + (size_t)(t0 + row) * 64 + seg * 4));
        }
    }
    CP_COMMIT();
    // prefetch B chunk 1 (group 1)
    load_B_chunk(sb, 1, 1, tid);
    CP_COMMIT();

    // ---- produce blended half of A tile (64 x 128) as fp16, swizzled ------
    {
        float slen = g_slens[b];
        float wv0 = g_w[0], wv1 = g_w[1], wv2 = g_w[2];
        const float* mrow = s_mask + (size_t)b * S_;
        int   ip[8], ic[8], in_[8];
        float w0a[8], w1a[8], w2a[8];
        #pragma unroll
        for (int i = 0; i < 8; i++) {
            int t = t0 + wid * 8 + i;
            float pos = (float)t * (1.0f / (float)(T_ - 1));
            float sp  = pos * (slen - 1.0f);
            int curr = (int)sp;
            ip[i] = max(curr - 1, 0);
            ic[i] = curr;
            in_[i] = min(curr + 1, S_ - 1);
        }
        #pragma unroll
        for (int i = 0; i < 8; i++) {
            w0a[i] = wv0 * mrow[ip[i]];
            w1a[i] = wv1 * mrow[ic[i]];
            w2a[i] = wv2 * mrow[in_[i]];
        }
        #pragma unroll 2
        for (int i = 0; i < 8; i++) {
            int row = wid * 8 + i;
            const float4* ep = (const float4*)(emb + ((size_t)b * S_ + ip[i]) * DIN);
            const float4* ec = (const float4*)(emb + ((size_t)b * S_ + ic[i]) * DIN);
            const float4* en = (const float4*)(emb + ((size_t)b * S_ + in_[i]) * DIN);
            float4 vp = ep[lane], vc = ec[lane], vn = en[lane];
            float w0 = w0a[i], w1 = w1a[i], w2 = w2a[i];
            float v0 = w0 * vp.x + w1 * vc.x + w2 * vn.x;
            float v1 = w0 * vp.y + w1 * vc.y + w2 * vn.y;
            float v2 = w0 * vp.z + w1 * vc.z + w2 * vn.z;
            float v3 = w0 * vp.w + w1 * vc.w + w2 * vn.w;
            __half2 hh0 = __floats2half2_rn(v0, v1);
            __half2 hh1 = __floats2half2_rn(v2, v3);
            uint32_t rbase = row * 512;
            uint32_t o1 = rbase + ((8 * lane) ^ ((row & 7) << 4));
            *(uint2*)(smem + OFF_A + o1) = make_uint2(h2u(hh0), h2u(hh1));
        }
    }

    // ---- ldmatrix lane addressing ----
    int xr = (lane & 7) + ((lane >> 3) & 1) * 8;   // 0..15
    int xg = lane >> 4;                            // 0..1
    int a_row = wm * 32 + xr;
    uint32_t a_base = sb + OFF_A + a_row * 512;
    uint32_t a_xor  = ((a_row & 7) << 4) ^ (xg * 16);
    uint32_t b_base = xr * 512;
    uint32_t b_xor  = (xr & 7) << 4;
    int b_col = wn * 128 + xg * 16;
    uint32_t co[4];
    #pragma unroll
    for (int p = 0; p < 4; p++) co[p] = ((uint32_t)(b_col + p * 32) ^ b_xor) + b_base;

    float acc[2][8][4];
    #pragma unroll
    for (int mt = 0; mt < 2; mt++)
        #pragma unroll
        for (int nt = 0; nt < 8; nt++)
            #pragma unroll
            for (int c = 0; c < 4; c++) acc[mt][nt][c] = 0.f;

    // ---- mainloop: 4 chunks of K=64, double-buffered ----------------------
    #pragma unroll
    for (int kc = 0; kc < 4; kc++) {
        CP_WAIT0();
        __syncthreads();
        if (kc < 3) {
            load_B_chunk(sb, (kc + 1) & 1, kc + 1, tid);
            CP_COMMIT();
        }
        uint32_t bstage = sb + OFF_B0 + (kc & 1) * B_STAGE;
        #pragma unroll
        for (int kk = 0; kk < 4; kk++) {
            uint32_t aoff = ((uint32_t)(kc * 128 + kk * 32)) ^ a_xor;
            uint32_t A0[4], A1[4];
            LDSM4(A0, a_base + aoff);
            LDSM4(A1, a_base + 16 * 512 + aoff);
            uint32_t bk = bstage + kk * 16 * 512;
            #pragma unroll
            for (int p = 0; p < 4; p++) {
                uint32_t Bf[4];
                LDSM4T(Bf, bk + co[p]);
                mma_f16(acc[0][2 * p],     A0, &Bf[0]);
                mma_f16(acc[0][2 * p + 1], A0, &Bf[2]);
                mma_f16(acc[1][2 * p],     A1, &Bf[0]);
                mma_f16(acc[1][2 * p + 1], A1, &Bf[2]);
            }
        }
    }
    __syncthreads();   // pipeline drained -> B region free for LN overlay

    // ---- epilogue: gelu + layernorm + mask (params straight from gmem) ----
    float* ps   = (float*)(smem + OFF_PS);
    float* ps2  = (float*)(smem + OFF_PS2);

    float2 bia[8], gg[8], be[8];
    #pragma unroll
    for (int nt = 0; nt < 8; nt++) {
        int c = wn * 64 + nt * 8 + 2 * (lane & 3);
        bia[nt] = *(const float2*)&bias[c];
        gg[nt]  = *(const float2*)&lng[c];
        be[nt]  = *(const float2*)&lnb[c];
    }

    #pragma unroll
    for (int mt = 0; mt < 2; mt++) {
        float sA = 0.f, s2A = 0.f, sB = 0.f, s2B = 0.f;
        #pragma unroll
        for (int nt = 0; nt < 8; nt++) {
            float v0 = gelu_exact(acc[mt][nt][0] + bia[nt].x);
            float v1 = gelu_exact(acc[mt][nt][1] + bia[nt].y);
            float v2 = gelu_exact(acc[mt][nt][2] + bia[nt].x);
            float v3 = gelu_exact(acc[mt][nt][3] + bia[nt].y);
            acc[mt][nt][0] = v0; acc[mt][nt][1] = v1;
            acc[mt][nt][2] = v2; acc[mt][nt][3] = v3;
            sA += v0 + v1; s2A += v0 * v0 + v1 * v1;
            sB += v2 + v3; s2B += v2 * v2 + v3 * v3;
        }
        #pragma unroll
        for (int o = 1; o <= 2; o <<= 1) {
            sA  += __shfl_xor_sync(0xFFFFFFFFu, sA,  o);
            s2A += __shfl_xor_sync(0xFFFFFFFFu, s2A, o);
            sB  += __shfl_xor_sync(0xFFFFFFFFu, sB,  o);
            s2B += __shfl_xor_sync(0xFFFFFFFFu, s2B, o);
        }
        if ((lane & 3) == 0) {
            int rA = wm * 32 + mt * 16 + (lane >> 2);
            ps[rA * 4 + wn]  = sA;  ps2[rA * 4 + wn]  = s2A;
            ps[(rA + 8) * 4 + wn] = sB; ps2[(rA + 8) * 4 + wn] = s2B;
        }
    }
    __syncthreads();

    #pragma unroll
    for (int mt = 0; mt < 2; mt++) {
        int rA = wm * 32 + mt * 16 + (lane >> 2);
        int rB = rA + 8;
        float tsA  = ps[rA * 4] + ps[rA * 4 + 1] + ps[rA * 4 + 2] + ps[rA * 4 + 3];
        float ts2A = ps2[rA * 4] + ps2[rA * 4 + 1] + ps2[rA * 4 + 2] + ps2[rA * 4 + 3];
        float tsB  = ps[rB * 4] + ps[rB * 4 + 1] + ps[rB * 4 + 2] + ps[rB * 4 + 3];
        float ts2B = ps2[rB * 4] + ps2[rB * 4 + 1] + ps2[rB * 4 + 2] + ps2[rB * 4 + 3];
        float muA = tsA * (1.f / 256.f);
        float muB = tsB * (1.f / 256.f);
        float invA = rsqrtf(ts2A * (1.f / 256.f) - muA * muA + 1e-5f);
        float invB = rsqrtf(ts2B * (1.f / 256.f) - muB * muB + 1e-5f);
        float mkA = tmask[m0 + rA];
        float mkB = tmask[m0 + rB];
        #pragma unroll
        for (int nt = 0; nt < 8; nt++) {
            int c = wn * 64 + nt * 8 + 2 * (lane & 3);
            float2 o1, o2;
            o1.x = ((acc[mt][nt][0] - muA) * invA * gg[nt].x + be[nt].x) * mkA;
            o1.y = ((acc[mt][nt][1] - muA) * invA * gg[nt].y + be[nt].y) * mkA;
            o2.x = ((acc[mt][nt][2] - muB) * invB * gg[nt].x + be[nt].x) * mkB;
            o2.y = ((acc[mt][nt][3] - muB) * invB * gg[nt].y + be[nt].y) * mkB;
            *(float2*)(out + (size_t)(m0 + rA) * DT + c) = o1;
            *(float2*)(out + (size_t)(m0 + rB) * DT + c) = o2;
        }
    }
}

// ---------------- launch ---------------------------------------------------
extern "C" void kernel_launch(void* const* d_in, const int* in_sizes, int n_in,
                              void* d_out, int out_size) {
    const float* student_emb = (const float*)d_in[0];
    const float* s_mask      = (const float*)d_in[1];
    const float* t_mask      = (const float*)d_in[2];
    int p = (in_sizes[3] == 64) ? 3 : 4;
    const float* pe_w1 = (const float*)d_in[p + 0];
    const float* pe_b1 = (const float*)d_in[p + 1];
    const float* pe_w2 = (const float*)d_in[p + 2];
    const float* pe_b2 = (const float*)d_in[p + 3];
    const float* pt_w  = (const float*)d_in[p + 4];
    const float* pt_b  = (const float*)d_in[p + 5];
    const float* ln_g  = (const float*)d_in[p + 6];
    const float* ln_b  = (const float*)d_in[p + 7];
    const float* nw    = (const float*)d_in[p + 8];
    float* out = (float*)d_out;

    cudaFuncSetAttribute(k_main, cudaFuncAttributeMaxDynamicSharedMemorySize, SMEM_TOTAL);

    k_prep<<<1, 1024>>>(s_mask, nw);
    k_posemb<<<T_, 128>>>(pe_w1, pe_b1, pe_w2, pe_b2);
    k_wsplit<<<DT * DT / 256, 256>>>(pt_w);
    k_main<<<NBLK, 256, SMEM_TOTAL>>>(student_emb, s_mask, t_mask,
                                      pt_b, ln_g, ln_b, out);
}

// round 12
// speedup vs baseline: 1.1648x; 1.0423x over previous
#include <cuda_runtime.h>
#include <cuda_fp16.h>
#include <cstdint>

#define B_   32
#define S_   4096
#define T_   8192
#define DIN  128
#define DT   256
#define M_   (B_ * T_)        // 262144
#define TILE_M 64
#define NBLK  (M_ / TILE_M)   // 4096

// ---------------- device-global tables (no runtime allocation) -------------
__device__ float    g_slens[B_];
__device__ float    g_w[4];
__device__ uint16_t g_wh[DT * DT];      // W fp16 (rounded), [k][n] row-major
__device__ uint32_t g_peh[T_ * 64];     // pos_emb packed fp16x2, [t][pair] (256B/row)

// ---------------- smem layout (swizzled, pitch 512) ------------------------
#define OFF_A    0              // 64 rows x 512 B (fp16: 256 cols)
#define OFF_B0   32768
#define B_STAGE  16384          // 32 k-rows x 512 B (one K32 chunk)
#define SMEM_TOTAL (OFF_B0 + 3 * B_STAGE)   // 81920 -> 2 CTAs/SM
// epilogue overlays (valid after final mainloop barrier; pipeline drained):
#define OFF_PS   OFF_B0
#define OFF_PS2  (OFF_B0 + 1024)

// ---------------- asm helpers ----------------------------------------------
__device__ __forceinline__ uint32_t smem_u32(const void* p) {
    uint32_t a;
    asm("{ .reg .u64 t; cvta.to.shared.u64 t, %1; cvt.u32.u64 %0, t; }" : "=r"(a) : "l"(p));
    return a;
}
#define CP_ASYNC16(dst, src) \
    asm volatile("cp.async.cg.shared.global [%0], [%1], 16;" :: "r"(dst), "l"(src))
#define CP_COMMIT() asm volatile("cp.async.commit_group;" ::: "memory")
#define CP_WAIT0()  asm volatile("cp.async.wait_group 0;" ::: "memory")
#define CP_WAIT1()  asm volatile("cp.async.wait_group 1;" ::: "memory")

#define LDSM4(r, addr) \
    asm volatile("ldmatrix.sync.aligned.m8n8.x4.shared.b16 {%0,%1,%2,%3}, [%4];" \
        : "=r"((r)[0]), "=r"((r)[1]), "=r"((r)[2]), "=r"((r)[3]) : "r"(addr))
#define LDSM4T(r, addr) \
    asm volatile("ldmatrix.sync.aligned.m8n8.x4.trans.shared.b16 {%0,%1,%2,%3}, [%4];" \
        : "=r"((r)[0]), "=r"((r)[1]), "=r"((r)[2]), "=r"((r)[3]) : "r"(addr))

// NOTE: not volatile -> ptxas is free to schedule/pipeline MMAs.
__device__ __forceinline__ void mma_f16(float* c, const uint32_t* a, const uint32_t* b) {
    asm("mma.sync.aligned.m16n8k16.row.col.f32.f16.f16.f32 "
        "{%0,%1,%2,%3}, {%4,%5,%6,%7}, {%8,%9}, {%0,%1,%2,%3};"
        : "+f"(c[0]), "+f"(c[1]), "+f"(c[2]), "+f"(c[3])
        : "r"(a[0]), "r"(a[1]), "r"(a[2]), "r"(a[3]), "r"(b[0]), "r"(b[1]));
}

__device__ __forceinline__ uint32_t h2u(__half2 h) {
    uint32_t u; *(__half2*)&u = h; return u;
}

__device__ __forceinline__ float gelu_exact(float x) {
    return 0.5f * x * (1.0f + erff(x * 0.70710678118654752440f));
}

// ---------------- kernel 1: s_lens (32 blocks) + neighbor softmax ----------
__global__ void k_prep(const float* __restrict__ s_mask, const float* __restrict__ nw) {
    __shared__ float part[8];
    int tid = threadIdx.x, w = tid >> 5, lane = tid & 31;
    const float* row = s_mask + (size_t)blockIdx.x * S_;
    float s = 0.f;
    #pragma unroll 4
    for (int i = tid; i < S_; i += 256) s += row[i];
    #pragma unroll
    for (int o = 16; o; o >>= 1) s += __shfl_xor_sync(0xFFFFFFFFu, s, o);
    if (lane == 0) part[w] = s;
    __syncthreads();
    if (tid == 0) {
        float t = 0.f;
        #pragma unroll
        for (int i = 0; i < 8; i++) t += part[i];
        g_slens[blockIdx.x] = t;
        if (blockIdx.x == 0) {
            float a = nw[0], b = nw[1], c = nw[2];
            float m = fmaxf(a, fmaxf(b, c));
            float ea = expf(a - m), eb = expf(b - m), ec = expf(c - m);
            float inv = 1.f / (ea + eb + ec);
            g_w[0] = ea * inv; g_w[1] = eb * inv; g_w[2] = ec * inv;
        }
    }
}

// ---------------- kernel 2: pos_emb -> packed fp16x2 [t][64] ---------------
// 256 blocks x 256 threads; w2 staged in smem ONCE per block (kills the
// 256 MB L2 re-read of the old per-t-block version). Each block: 32 t rows.
__global__ void __launch_bounds__(256)
k_posemb(const float* __restrict__ w1, const float* __restrict__ b1,
         const float* __restrict__ w2, const float* __restrict__ b2) {
    __shared__ float2 w2s[64 * 64];      // 32 KB: w2[j][2dp..2dp+1]
    __shared__ float  hs[32][64];        // 8 KB: gelu(pos*w1+b1)
    int tid = threadIdx.x;
    int t0b = blockIdx.x * 32;
    const float step = 1.0f / (float)(T_ - 1);

    // stage w2 (8192 floats = 4096 float2)
    const float2* w2v = (const float2*)w2;
    #pragma unroll
    for (int i = 0; i < 16; i++) w2s[tid + 256 * i] = w2v[tid + 256 * i];

    // h: 32 t x 64 j = 2048 gelu, 8 per thread
    #pragma unroll
    for (int i = 0; i < 8; i++) {
        int idx = tid + 256 * i;
        int tt = idx >> 6, j = idx & 63;
        float pos = (float)(t0b + tt) * step;
        hs[tt][j] = gelu_exact(pos * w1[j] + b1[j]);
    }
    __syncthreads();

    // outputs: thread owns dpair = tid&63; ttgroup = tid>>6; 8 passes x 4 tt
    int dp = tid & 63, tg = tid >> 6;
    float b2a = b2[2 * dp], b2b = b2[2 * dp + 1];
    #pragma unroll
    for (int p = 0; p < 8; p++) {
        int tt = tg + 4 * p;
        float a0 = b2a, a1 = b2b;
        #pragma unroll 16
        for (int j = 0; j < 64; j++) {
            float hv = hs[tt][j];
            float2 w = w2s[j * 64 + dp];
            a0 = fmaf(hv, w.x, a0);
            a1 = fmaf(hv, w.y, a1);
        }
        g_peh[(size_t)(t0b + tt) * 64 + dp] = h2u(__floats2half2_rn(a0, a1));
    }
}

// ---------------- kernel 3: W -> fp16 (rounded) [k][n] ---------------------
__global__ void k_wsplit(const float* __restrict__ W) {
    int idx = blockIdx.x * 256 + threadIdx.x;   // 65536
    __half h = __float2half_rn(W[idx]);
    g_wh[idx] = *(uint16_t*)&h;
}

// ---------------- B chunk loader: K=32, swizzled, cp.async (16KB) ----------
__device__ __forceinline__ void load_B_chunk(uint32_t sb, int stage, int chunk, int tid) {
    uint32_t dst = sb + OFF_B0 + stage * B_STAGE;
    const char* src0 = (const char*)(g_wh + chunk * 32 * DT);
    #pragma unroll
    for (int i = 0; i < 4; i++) {
        int f = tid + 256 * i;             // 0..1023
        int r = f >> 5;                    // K row within chunk (0..31)
        int c = f & 31;                    // 16B segment
        CP_ASYNC16(dst + r * 512 + ((c ^ (r & 7)) << 4), src0 + (size_t)r * 512 + c * 16);
    }
}

// ---------------- kernel 4: fused gather + fp16 GEMM + epilogue ------------
__global__ void __launch_bounds__(256, 2)
k_main(const float* __restrict__ emb, const float* __restrict__ s_mask,
       const float* __restrict__ tmask,
       const float* __restrict__ bias, const float* __restrict__ lng,
       const float* __restrict__ lnb, float* __restrict__ out) {
    extern __shared__ char smem[];
    uint32_t sb = smem_u32(smem);
    int tid = threadIdx.x, wid = tid >> 5, lane = tid & 31;
    int wm = wid >> 2;        // 0..1 : M half (32 rows)
    int wn = wid & 3;         // 0..3 : N quarter (64 cols)
    int m0 = blockIdx.x * TILE_M;
    int t0 = m0 & (T_ - 1);   // all 64 rows share batch b
    int b  = m0 >> 13;

    // early exit: t_mask is a prefix mask -> whole block exactly zero.
    if (tmask[m0] == 0.f) {
        float4 z = make_float4(0.f, 0.f, 0.f, 0.f);
        float4* o4 = (float4*)(out + (size_t)m0 * DT);
        #pragma unroll
        for (int i = 0; i < 16; i++) o4[tid + 256 * i] = z;
        return;
    }

    // group 0: B chunk 0 + pos_emb half of A (cols 128..255, swizzled)
    load_B_chunk(sb, 0, 0, tid);
    {
        #pragma unroll
        for (int i = 0; i < 4; i++) {
            int f = tid + 256 * i;         // 0..1023
            int row = f >> 4;              // 0..63
            int seg = f & 15;              // 16B segment within 256B
            uint32_t byte = (uint32_t)(256 + seg * 16) ^ ((row & 7) << 4);
            CP_ASYNC16(sb + OFF_A + row * 512 + byte,
                       (const char*)(g_peh + (size_t)(t0 + row) * 64 + seg * 4));
        }
    }
    CP_COMMIT();
    // group 1: B chunk 1
    load_B_chunk(sb, 1, 1, tid);
    CP_COMMIT();

    // ---- produce blended half of A tile (64 x 128) as fp16, swizzled ------
    {
        float slen = g_slens[b];
        float wv0 = g_w[0], wv1 = g_w[1], wv2 = g_w[2];
        const float* mrow = s_mask + (size_t)b * S_;
        int   ip[8], ic[8], in_[8];
        float w0a[8], w1a[8], w2a[8];
        #pragma unroll
        for (int i = 0; i < 8; i++) {
            int t = t0 + wid * 8 + i;
            float pos = (float)t * (1.0f / (float)(T_ - 1));
            float sp  = pos * (slen - 1.0f);
            int curr = (int)sp;
            ip[i] = max(curr - 1, 0);
            ic[i] = curr;
            in_[i] = min(curr + 1, S_ - 1);
        }
        #pragma unroll
        for (int i = 0; i < 8; i++) {
            w0a[i] = wv0 * mrow[ip[i]];
            w1a[i] = wv1 * mrow[ic[i]];
            w2a[i] = wv2 * mrow[in_[i]];
        }
        #pragma unroll 2
        for (int i = 0; i < 8; i++) {
            int row = wid * 8 + i;
            const float4* ep = (const float4*)(emb + ((size_t)b * S_ + ip[i]) * DIN);
            const float4* ec = (const float4*)(emb + ((size_t)b * S_ + ic[i]) * DIN);
            const float4* en = (const float4*)(emb + ((size_t)b * S_ + in_[i]) * DIN);
            float4 vp = ep[lane], vc = ec[lane], vn = en[lane];
            float w0 = w0a[i], w1 = w1a[i], w2 = w2a[i];
            float v0 = w0 * vp.x + w1 * vc.x + w2 * vn.x;
            float v1 = w0 * vp.y + w1 * vc.y + w2 * vn.y;
            float v2 = w0 * vp.z + w1 * vc.z + w2 * vn.z;
            float v3 = w0 * vp.w + w1 * vc.w + w2 * vn.w;
            __half2 hh0 = __floats2half2_rn(v0, v1);
            __half2 hh1 = __floats2half2_rn(v2, v3);
            uint32_t rbase = row * 512;
            uint32_t o1 = rbase + ((8 * lane) ^ ((row & 7) << 4));
            *(uint2*)(smem + OFF_A + o1) = make_uint2(h2u(hh0), h2u(hh1));
        }
    }

    // ---- ldmatrix lane addressing ----
    int xr = (lane & 7) + ((lane >> 3) & 1) * 8;   // 0..15
    int xg = lane >> 4;                            // 0..1
    int a_row = wm * 32 + xr;
    uint32_t a_base = sb + OFF_A + a_row * 512;
    uint32_t a_xor  = ((a_row & 7) << 4) ^ (xg * 16);
    uint32_t b_base = xr * 512;
    uint32_t b_xor  = (xr & 7) << 4;
    int b_col = wn * 128 + xg * 16;
    uint32_t co[4];
    #pragma unroll
    for (int p = 0; p < 4; p++) co[p] = ((uint32_t)(b_col + p * 32) ^ b_xor) + b_base;

    float acc[2][8][4];
    #pragma unroll
    for (int mt = 0; mt < 2; mt++)
        #pragma unroll
        for (int nt = 0; nt < 8; nt++)
            #pragma unroll
            for (int c = 0; c < 4; c++) acc[mt][nt][c] = 0.f;

    // ---- mainloop: 8 chunks of K=32, 3-stage pipeline ---------------------
    int st = 0;
    for (int kc = 0; kc < 8; kc++) {
        if (kc == 7) { CP_WAIT0(); } else { CP_WAIT1(); }
        __syncthreads();
        if (kc < 6) {
            int nst = st + 2; if (nst >= 3) nst -= 3;
            load_B_chunk(sb, nst, kc + 2, tid);
            CP_COMMIT();
        }
        uint32_t bstage = sb + OFF_B0 + st * B_STAGE;
        #pragma unroll
        for (int kk = 0; kk < 2; kk++) {
            uint32_t aoff = ((uint32_t)(kc * 64 + kk * 32)) ^ a_xor;
            uint32_t A0[4], A1[4];
            LDSM4(A0, a_base + aoff);
            LDSM4(A1, a_base + 16 * 512 + aoff);
            uint32_t bk = bstage + kk * 16 * 512;
            #pragma unroll
            for (int p = 0; p < 4; p++) {
                uint32_t Bf[4];
                LDSM4T(Bf, bk + co[p]);
                mma_f16(acc[0][2 * p],     A0, &Bf[0]);
                mma_f16(acc[0][2 * p + 1], A0, &Bf[2]);
                mma_f16(acc[1][2 * p],     A1, &Bf[0]);
                mma_f16(acc[1][2 * p + 1], A1, &Bf[2]);
            }
        }
        st = (st == 2) ? 0 : st + 1;
    }
    __syncthreads();   // pipeline drained -> B region free for LN overlay

    // ---- epilogue: gelu + layernorm + mask (params straight from gmem) ----
    float* ps   = (float*)(smem + OFF_PS);
    float* ps2  = (float*)(smem + OFF_PS2);

    float2 bia[8], gg[8], be[8];
    #pragma unroll
    for (int nt = 0; nt < 8; nt++) {
        int c = wn * 64 + nt * 8 + 2 * (lane & 3);
        bia[nt] = *(const float2*)&bias[c];
        gg[nt]  = *(const float2*)&lng[c];
        be[nt]  = *(const float2*)&lnb[c];
    }

    #pragma unroll
    for (int mt = 0; mt < 2; mt++) {
        float sA = 0.f, s2A = 0.f, sB = 0.f, s2B = 0.f;
        #pragma unroll
        for (int nt = 0; nt < 8; nt++) {
            float v0 = gelu_exact(acc[mt][nt][0] + bia[nt].x);
            float v1 = gelu_exact(acc[mt][nt][1] + bia[nt].y);
            float v2 = gelu_exact(acc[mt][nt][2] + bia[nt].x);
            float v3 = gelu_exact(acc[mt][nt][3] + bia[nt].y);
            acc[mt][nt][0] = v0; acc[mt][nt][1] = v1;
            acc[mt][nt][2] = v2; acc[mt][nt][3] = v3;
            sA += v0 + v1; s2A += v0 * v0 + v1 * v1;
            sB += v2 + v3; s2B += v2 * v2 + v3 * v3;
        }
        #pragma unroll
        for (int o = 1; o <= 2; o <<= 1) {
            sA  += __shfl_xor_sync(0xFFFFFFFFu, sA,  o);
            s2A += __shfl_xor_sync(0xFFFFFFFFu, s2A, o);
            sB  += __shfl_xor_sync(0xFFFFFFFFu, sB,  o);
            s2B += __shfl_xor_sync(0xFFFFFFFFu, s2B, o);
        }
        if ((lane & 3) == 0) {
            int rA = wm * 32 + mt * 16 + (lane >> 2);
            ps[rA * 4 + wn]  = sA;  ps2[rA * 4 + wn]  = s2A;
            ps[(rA + 8) * 4 + wn] = sB; ps2[(rA + 8) * 4 + wn] = s2B;
        }
    }
    __syncthreads();

    #pragma unroll
    for (int mt = 0; mt < 2; mt++) {
        int rA = wm * 32 + mt * 16 + (lane >> 2);
        int rB = rA + 8;
        float tsA  = ps[rA * 4] + ps[rA * 4 + 1] + ps[rA * 4 + 2] + ps[rA * 4 + 3];
        float ts2A = ps2[rA * 4] + ps2[rA * 4 + 1] + ps2[rA * 4 + 2] + ps2[rA * 4 + 3];
        float tsB  = ps[rB * 4] + ps[rB * 4 + 1] + ps[rB * 4 + 2] + ps[rB * 4 + 3];
        float ts2B = ps2[rB * 4] + ps2[rB * 4 + 1] + ps2[rB * 4 + 2] + ps2[rB * 4 + 3];
        float muA = tsA * (1.f / 256.f);
        float muB = tsB * (1.f / 256.f);
        float invA = rsqrtf(ts2A * (1.f / 256.f) - muA * muA + 1e-5f);
        float invB = rsqrtf(ts2B * (1.f / 256.f) - muB * muB + 1e-5f);
        float mkA = tmask[m0 + rA];
        float mkB = tmask[m0 + rB];
        #pragma unroll
        for (int nt = 0; nt < 8; nt++) {
            int c = wn * 64 + nt * 8 + 2 * (lane & 3);
            float2 o1, o2;
            o1.x = ((acc[mt][nt][0] - muA) * invA * gg[nt].x + be[nt].x) * mkA;
            o1.y = ((acc[mt][nt][1] - muA) * invA * gg[nt].y + be[nt].y) * mkA;
            o2.x = ((acc[mt][nt][2] - muB) * invB * gg[nt].x + be[nt].x) * mkB;
            o2.y = ((acc[mt][nt][3] - muB) * invB * gg[nt].y + be[nt].y) * mkB;
            *(float2*)(out + (size_t)(m0 + rA) * DT + c) = o1;
            *(float2*)(out + (size_t)(m0 + rB) * DT + c) = o2;
        }
    }
}

// ---------------- launch ---------------------------------------------------
extern "C" void kernel_launch(void* const* d_in, const int* in_sizes, int n_in,
                              void* d_out, int out_size) {
    const float* student_emb = (const float*)d_in[0];
    const float* s_mask      = (const float*)d_in[1];
    const float* t_mask      = (const float*)d_in[2];
    int p = (in_sizes[3] == 64) ? 3 : 4;
    const float* pe_w1 = (const float*)d_in[p + 0];
    const float* pe_b1 = (const float*)d_in[p + 1];
    const float* pe_w2 = (const float*)d_in[p + 2];
    const float* pe_b2 = (const float*)d_in[p + 3];
    const float* pt_w  = (const float*)d_in[p + 4];
    const float* pt_b  = (const float*)d_in[p + 5];
    const float* ln_g  = (const float*)d_in[p + 6];
    const float* ln_b  = (const float*)d_in[p + 7];
    const float* nw    = (const float*)d_in[p + 8];
    float* out = (float*)d_out;

    cudaFuncSetAttribute(k_main, cudaFuncAttributeMaxDynamicSharedMemorySize, SMEM_TOTAL);

    k_prep<<<B_, 256>>>(s_mask, nw);
    k_posemb<<<T_ / 32, 256>>>(pe_w1, pe_b1, pe_w2, pe_b2);
    k_wsplit<<<DT * DT / 256, 256>>>(pt_w);
    k_main<<<NBLK, 256, SMEM_TOTAL>>>(student_emb, s_mask, t_mask,
                                      pt_b, ln_g, ln_b, out);
}

// round 13
// speedup vs baseline: 1.2101x; 1.0390x over previous
#include <cuda_runtime.h>
#include <cuda_fp16.h>
#include <cstdint>

#define B_   32
#define S_   4096
#define T_   8192
#define DIN  128
#define DT   256
#define M_   (B_ * T_)        // 262144
#define TILE_M 64
#define NBLK  (M_ / TILE_M)   // 4096

// ---------------- device-global tables (no runtime allocation) -------------
__device__ float    g_slens[B_];
__device__ float    g_w[4];
__device__ uint16_t g_wh[DT * DT];      // W fp16 (rounded), [k][n] row-major
__device__ uint32_t g_peh[T_ * 64];     // pos_emb packed fp16x2, [t][pair] (256B/row)

// ---------------- smem layout (swizzled, pitch 512) ------------------------
#define OFF_A    0              // 64 rows x 512 B (fp16: 256 cols)
#define OFF_B0   32768
#define B_STAGE  16384          // 32 k-rows x 512 B (one K32 chunk)
#define OFF_PRM  (OFF_B0 + 3 * B_STAGE)     // 81920: bias/g/beta, 3 KB
#define SMEM_TOTAL (OFF_PRM + 3072)         // 84992 -> 2 CTAs/SM
// epilogue overlays (valid after final mainloop barrier; pipeline drained):
#define OFF_PS   OFF_B0
#define OFF_PS2  (OFF_B0 + 1024)

// ---------------- asm helpers ----------------------------------------------
__device__ __forceinline__ uint32_t smem_u32(const void* p) {
    uint32_t a;
    asm("{ .reg .u64 t; cvta.to.shared.u64 t, %1; cvt.u32.u64 %0, t; }" : "=r"(a) : "l"(p));
    return a;
}
#define CP_ASYNC16(dst, src) \
    asm volatile("cp.async.cg.shared.global [%0], [%1], 16;" :: "r"(dst), "l"(src))
#define CP_COMMIT() asm volatile("cp.async.commit_group;" ::: "memory")
#define CP_WAIT0()  asm volatile("cp.async.wait_group 0;" ::: "memory")
#define CP_WAIT1()  asm volatile("cp.async.wait_group 1;" ::: "memory")

#define LDSM4(r, addr) \
    asm volatile("ldmatrix.sync.aligned.m8n8.x4.shared.b16 {%0,%1,%2,%3}, [%4];" \
        : "=r"((r)[0]), "=r"((r)[1]), "=r"((r)[2]), "=r"((r)[3]) : "r"(addr))
#define LDSM4T(r, addr) \
    asm volatile("ldmatrix.sync.aligned.m8n8.x4.trans.shared.b16 {%0,%1,%2,%3}, [%4];" \
        : "=r"((r)[0]), "=r"((r)[1]), "=r"((r)[2]), "=r"((r)[3]) : "r"(addr))

// NOTE: not volatile -> ptxas is free to schedule/pipeline MMAs.
__device__ __forceinline__ void mma_f16(float* c, const uint32_t* a, const uint32_t* b) {
    asm("mma.sync.aligned.m16n8k16.row.col.f32.f16.f16.f32 "
        "{%0,%1,%2,%3}, {%4,%5,%6,%7}, {%8,%9}, {%0,%1,%2,%3};"
        : "+f"(c[0]), "+f"(c[1]), "+f"(c[2]), "+f"(c[3])
        : "r"(a[0]), "r"(a[1]), "r"(a[2]), "r"(a[3]), "r"(b[0]), "r"(b[1]));
}

__device__ __forceinline__ uint32_t h2u(__half2 h) {
    uint32_t u; *(__half2*)&u = h; return u;
}

__device__ __forceinline__ float gelu_exact(float x) {
    return 0.5f * x * (1.0f + erff(x * 0.70710678118654752440f));
}

// ---------------- fused prep kernel ----------------------------------------
// blocks 0..255   : pos_emb table (32 t-rows each; w2 staged in smem)
// blocks 256..287 : s_lens (one batch row each); block 256 also softmax(nw)
// blocks 288..319 : W -> fp16 (2048 elements each)
__global__ void __launch_bounds__(256)
k_prep_all(const float* __restrict__ s_mask, const float* __restrict__ nw,
           const float* __restrict__ W,
           const float* __restrict__ w1, const float* __restrict__ b1,
           const float* __restrict__ w2, const float* __restrict__ b2) {
    __shared__ float2 w2s[64 * 64];      // 32 KB
    __shared__ float  hs[32][64];        // 8 KB
    int tid = threadIdx.x;
    int blk = blockIdx.x;

    if (blk < 256) {
        // ---- pos_emb ----
        int t0b = blk * 32;
        const float step = 1.0f / (float)(T_ - 1);
        const float2* w2v = (const float2*)w2;
        #pragma unroll
        for (int i = 0; i < 16; i++) w2s[tid + 256 * i] = w2v[tid + 256 * i];
        #pragma unroll
        for (int i = 0; i < 8; i++) {
            int idx = tid + 256 * i;
            int tt = idx >> 6, j = idx & 63;
            float pos = (float)(t0b + tt) * step;
            hs[tt][j] = gelu_exact(pos * w1[j] + b1[j]);
        }
        __syncthreads();
        int dp = tid & 63, tg = tid >> 6;
        float b2a = b2[2 * dp], b2b = b2[2 * dp + 1];
        #pragma unroll
        for (int p = 0; p < 8; p++) {
            int tt = tg + 4 * p;
            float a0 = b2a, a1 = b2b;
            #pragma unroll 16
            for (int j = 0; j < 64; j++) {
                float hv = hs[tt][j];
                float2 w = w2s[j * 64 + dp];
                a0 = fmaf(hv, w.x, a0);
                a1 = fmaf(hv, w.y, a1);
            }
            g_peh[(size_t)(t0b + tt) * 64 + dp] = h2u(__floats2half2_rn(a0, a1));
        }
    } else if (blk < 288) {
        // ---- s_lens ----
        int bb = blk - 256;
        float* part = (float*)w2s;
        int w = tid >> 5, lane = tid & 31;
        const float* row = s_mask + (size_t)bb * S_;
        float s = 0.f;
        #pragma unroll 4
        for (int i = tid; i < S_; i += 256) s += row[i];
        #pragma unroll
        for (int o = 16; o; o >>= 1) s += __shfl_xor_sync(0xFFFFFFFFu, s, o);
        if (lane == 0) part[w] = s;
        __syncthreads();
        if (tid == 0) {
            float t = 0.f;
            #pragma unroll
            for (int i = 0; i < 8; i++) t += part[i];
            g_slens[bb] = t;
            if (bb == 0) {
                float a = nw[0], b = nw[1], c = nw[2];
                float m = fmaxf(a, fmaxf(b, c));
                float ea = expf(a - m), eb = expf(b - m), ec = expf(c - m);
                float inv = 1.f / (ea + eb + ec);
                g_w[0] = ea * inv; g_w[1] = eb * inv; g_w[2] = ec * inv;
            }
        }
    } else {
        // ---- W -> fp16 ----
        int base = (blk - 288) * 2048;
        #pragma unroll
        for (int i = 0; i < 8; i++) {
            int idx = base + tid + 256 * i;
            __half h = __float2half_rn(W[idx]);
            g_wh[idx] = *(uint16_t*)&h;
        }
    }
}

// ---------------- B chunk loader: K=32, swizzled, cp.async (16KB) ----------
__device__ __forceinline__ void load_B_chunk(uint32_t sb, int stage, int chunk, int tid) {
    uint32_t dst = sb + OFF_B0 + stage * B_STAGE;
    const char* src0 = (const char*)(g_wh + chunk * 32 * DT);
    #pragma unroll
    for (int i = 0; i < 4; i++) {
        int f = tid + 256 * i;             // 0..1023
        int r = f >> 5;                    // K row within chunk (0..31)
        int c = f & 31;                    // 16B segment
        CP_ASYNC16(dst + r * 512 + ((c ^ (r & 7)) << 4), src0 + (size_t)r * 512 + c * 16);
    }
}

// ---------------- main kernel: fused gather + fp16 GEMM + epilogue ---------
__global__ void __launch_bounds__(256, 2)
k_main(const float* __restrict__ emb, const float* __restrict__ s_mask,
       const float* __restrict__ tmask,
       const float* __restrict__ bias, const float* __restrict__ lng,
       const float* __restrict__ lnb, float* __restrict__ out) {
    extern __shared__ char smem[];
    uint32_t sb = smem_u32(smem);
    int tid = threadIdx.x, wid = tid >> 5, lane = tid & 31;
    int wm = wid >> 2;        // 0..1 : M half (32 rows)
    int wn = wid & 3;         // 0..3 : N quarter (64 cols)
    int m0 = blockIdx.x * TILE_M;
    int t0 = m0 & (T_ - 1);   // all 64 rows share batch b
    int b  = m0 >> 13;

    // early exit: t_mask is a prefix mask -> whole block exactly zero.
    if (tmask[m0] == 0.f) {
        float4 z = make_float4(0.f, 0.f, 0.f, 0.f);
        float4* o4 = (float4*)(out + (size_t)m0 * DT);
        #pragma unroll
        for (int i = 0; i < 16; i++) o4[tid + 256 * i] = z;
        return;
    }

    // group 0: B chunk 0 + pos_emb half of A + epilogue params
    load_B_chunk(sb, 0, 0, tid);
    {
        #pragma unroll
        for (int i = 0; i < 4; i++) {
            int f = tid + 256 * i;         // 0..1023
            int row = f >> 4;              // 0..63
            int seg = f & 15;              // 16B segment within 256B
            uint32_t byte = (uint32_t)(256 + seg * 16) ^ ((row & 7) << 4);
            CP_ASYNC16(sb + OFF_A + row * 512 + byte,
                       (const char*)(g_peh + (size_t)(t0 + row) * 64 + seg * 4));
        }
        // params: bias | lng | lnb -> 3 x 1024 B
        if (tid < 192) {
            int which = tid >> 6;          // 0..2
            int seg   = tid & 63;          // 16B segment
            const float* src = (which == 0) ? bias : (which == 1) ? lng : lnb;
            CP_ASYNC16(sb + OFF_PRM + which * 1024 + seg * 16, (const char*)(src + seg * 4));
        }
    }
    CP_COMMIT();
    // group 1: B chunk 1
    load_B_chunk(sb, 1, 1, tid);
    CP_COMMIT();

    // ---- produce blended half of A tile (64 x 128) as fp16, swizzled ------
    {
        float slen = g_slens[b];
        float wv0 = g_w[0], wv1 = g_w[1], wv2 = g_w[2];
        const float* mrow = s_mask + (size_t)b * S_;
        int   ip[8], ic[8], in_[8];
        float w0a[8], w1a[8], w2a[8];
        #pragma unroll
        for (int i = 0; i < 8; i++) {
            int t = t0 + wid * 8 + i;
            float pos = (float)t * (1.0f / (float)(T_ - 1));
            float sp  = pos * (slen - 1.0f);
            int curr = (int)sp;
            ip[i] = max(curr - 1, 0);
            ic[i] = curr;
            in_[i] = min(curr + 1, S_ - 1);
        }
        #pragma unroll
        for (int i = 0; i < 8; i++) {
            w0a[i] = wv0 * mrow[ip[i]];
            w1a[i] = wv1 * mrow[ic[i]];
            w2a[i] = wv2 * mrow[in_[i]];
        }
        #pragma unroll 2
        for (int i = 0; i < 8; i++) {
            int row = wid * 8 + i;
            const float4* ep = (const float4*)(emb + ((size_t)b * S_ + ip[i]) * DIN);
            const float4* ec = (const float4*)(emb + ((size_t)b * S_ + ic[i]) * DIN);
            const float4* en = (const float4*)(emb + ((size_t)b * S_ + in_[i]) * DIN);
            float4 vp = ep[lane], vc = ec[lane], vn = en[lane];
            float w0 = w0a[i], w1 = w1a[i], w2 = w2a[i];
            float v0 = w0 * vp.x + w1 * vc.x + w2 * vn.x;
            float v1 = w0 * vp.y + w1 * vc.y + w2 * vn.y;
            float v2 = w0 * vp.z + w1 * vc.z + w2 * vn.z;
            float v3 = w0 * vp.w + w1 * vc.w + w2 * vn.w;
            __half2 hh0 = __floats2half2_rn(v0, v1);
            __half2 hh1 = __floats2half2_rn(v2, v3);
            uint32_t rbase = row * 512;
            uint32_t o1 = rbase + ((8 * lane) ^ ((row & 7) << 4));
            *(uint2*)(smem + OFF_A + o1) = make_uint2(h2u(hh0), h2u(hh1));
        }
    }

    // ---- ldmatrix lane addressing ----
    int xr = (lane & 7) + ((lane >> 3) & 1) * 8;   // 0..15
    int xg = lane >> 4;                            // 0..1
    int a_row = wm * 32 + xr;
    uint32_t a_base = sb + OFF_A + a_row * 512;
    uint32_t a_xor  = ((a_row & 7) << 4) ^ (xg * 16);
    uint32_t b_base = xr * 512;
    uint32_t b_xor  = (xr & 7) << 4;
    int b_col = wn * 128 + xg * 16;
    uint32_t co[4];
    #pragma unroll
    for (int p = 0; p < 4; p++) co[p] = ((uint32_t)(b_col + p * 32) ^ b_xor) + b_base;

    float acc[2][8][4];
    #pragma unroll
    for (int mt = 0; mt < 2; mt++)
        #pragma unroll
        for (int nt = 0; nt < 8; nt++)
            #pragma unroll
            for (int c = 0; c < 4; c++) acc[mt][nt][c] = 0.f;

    // ---- mainloop: 8 chunks of K=32, 3-stage pipeline ---------------------
    int st = 0;
    for (int kc = 0; kc < 8; kc++) {
        if (kc == 7) { CP_WAIT0(); } else { CP_WAIT1(); }
        __syncthreads();
        if (kc < 6) {
            int nst = st + 2; if (nst >= 3) nst -= 3;
            load_B_chunk(sb, nst, kc + 2, tid);
            CP_COMMIT();
        }
        uint32_t bstage = sb + OFF_B0 + st * B_STAGE;
        #pragma unroll
        for (int kk = 0; kk < 2; kk++) {
            uint32_t aoff = ((uint32_t)(kc * 64 + kk * 32)) ^ a_xor;
            uint32_t A0[4], A1[4];
            LDSM4(A0, a_base + aoff);
            LDSM4(A1, a_base + 16 * 512 + aoff);
            uint32_t bk = bstage + kk * 16 * 512;
            #pragma unroll
            for (int p = 0; p < 4; p++) {
                uint32_t Bf[4];
                LDSM4T(Bf, bk + co[p]);
                mma_f16(acc[0][2 * p],     A0, &Bf[0]);
                mma_f16(acc[0][2 * p + 1], A0, &Bf[2]);
                mma_f16(acc[1][2 * p],     A1, &Bf[0]);
                mma_f16(acc[1][2 * p + 1], A1, &Bf[2]);
            }
        }
        st = (st == 2) ? 0 : st + 1;
    }
    __syncthreads();   // pipeline drained -> B region free for LN overlay

    // ---- epilogue: gelu + layernorm + mask (params from smem) -------------
    float* ps   = (float*)(smem + OFF_PS);
    float* ps2  = (float*)(smem + OFF_PS2);
    const float* smB  = (const float*)(smem + OFF_PRM);
    const float* smG  = (const float*)(smem + OFF_PRM + 1024);
    const float* smBe = (const float*)(smem + OFF_PRM + 2048);

    float2 bia[8], gg[8], be[8];
    #pragma unroll
    for (int nt = 0; nt < 8; nt++) {
        int c = wn * 64 + nt * 8 + 2 * (lane & 3);
        bia[nt] = *(const float2*)&smB[c];
        gg[nt]  = *(const float2*)&smG[c];
        be[nt]  = *(const float2*)&smBe[c];
    }

    #pragma unroll
    for (int mt = 0; mt < 2; mt++) {
        float sA = 0.f, s2A = 0.f, sB = 0.f, s2B = 0.f;
        #pragma unroll
        for (int nt = 0; nt < 8; nt++) {
            float v0 = gelu_exact(acc[mt][nt][0] + bia[nt].x);
            float v1 = gelu_exact(acc[mt][nt][1] + bia[nt].y);
            float v2 = gelu_exact(acc[mt][nt][2] + bia[nt].x);
            float v3 = gelu_exact(acc[mt][nt][3] + bia[nt].y);
            acc[mt][nt][0] = v0; acc[mt][nt][1] = v1;
            acc[mt][nt][2] = v2; acc[mt][nt][3] = v3;
            sA += v0 + v1; s2A += v0 * v0 + v1 * v1;
            sB += v2 + v3; s2B += v2 * v2 + v3 * v3;
        }
        #pragma unroll
        for (int o = 1; o <= 2; o <<= 1) {
            sA  += __shfl_xor_sync(0xFFFFFFFFu, sA,  o);
            s2A += __shfl_xor_sync(0xFFFFFFFFu, s2A, o);
            sB  += __shfl_xor_sync(0xFFFFFFFFu, sB,  o);
            s2B += __shfl_xor_sync(0xFFFFFFFFu, s2B, o);
        }
        if ((lane & 3) == 0) {
            int rA = wm * 32 + mt * 16 + (lane >> 2);
            ps[rA * 4 + wn]  = sA;  ps2[rA * 4 + wn]  = s2A;
            ps[(rA + 8) * 4 + wn] = sB; ps2[(rA + 8) * 4 + wn] = s2B;
        }
    }
    __syncthreads();

    #pragma unroll
    for (int mt = 0; mt < 2; mt++) {
        int rA = wm * 32 + mt * 16 + (lane >> 2);
        int rB = rA + 8;
        float tsA  = ps[rA * 4] + ps[rA * 4 + 1] + ps[rA * 4 + 2] + ps[rA * 4 + 3];
        float ts2A = ps2[rA * 4] + ps2[rA * 4 + 1] + ps2[rA * 4 + 2] + ps2[rA * 4 + 3];
        float tsB  = ps[rB * 4] + ps[rB * 4 + 1] + ps[rB * 4 + 2] + ps[rB * 4 + 3];
        float ts2B = ps2[rB * 4] + ps2[rB * 4 + 1] + ps2[rB * 4 + 2] + ps2[rB * 4 + 3];
        float muA = tsA * (1.f / 256.f);
        float muB = tsB * (1.f / 256.f);
        float invA = rsqrtf(ts2A * (1.f / 256.f) - muA * muA + 1e-5f);
        float invB = rsqrtf(ts2B * (1.f / 256.f) - muB * muB + 1e-5f);
        float mkA = tmask[m0 + rA];
        float mkB = tmask[m0 + rB];
        #pragma unroll
        for (int nt = 0; nt < 8; nt++) {
            int c = wn * 64 + nt * 8 + 2 * (lane & 3);
            float2 o1, o2;
            o1.x = ((acc[mt][nt][0] - muA) * invA * gg[nt].x + be[nt].x) * mkA;
            o1.y = ((acc[mt][nt][1] - muA) * invA * gg[nt].y + be[nt].y) * mkA;
            o2.x = ((acc[mt][nt][2] - muB) * invB * gg[nt].x + be[nt].x) * mkB;
            o2.y = ((acc[mt][nt][3] - muB) * invB * gg[nt].y + be[nt].y) * mkB;
            *(float2*)(out + (size_t)(m0 + rA) * DT + c) = o1;
            *(float2*)(out + (size_t)(m0 + rB) * DT + c) = o2;
        }
    }
}

// ---------------- launch ---------------------------------------------------
extern "C" void kernel_launch(void* const* d_in, const int* in_sizes, int n_in,
                              void* d_out, int out_size) {
    const float* student_emb = (const float*)d_in[0];
    const float* s_mask      = (const float*)d_in[1];
    const float* t_mask      = (const float*)d_in[2];
    int p = (in_sizes[3] == 64) ? 3 : 4;
    const float* pe_w1 = (const float*)d_in[p + 0];
    const float* pe_b1 = (const float*)d_in[p + 1];
    const float* pe_w2 = (const float*)d_in[p + 2];
    const float* pe_b2 = (const float*)d_in[p + 3];
    const float* pt_w  = (const float*)d_in[p + 4];
    const float* pt_b  = (const float*)d_in[p + 5];
    const float* ln_g  = (const float*)d_in[p + 6];
    const float* ln_b  = (const float*)d_in[p + 7];
    const float* nw    = (const float*)d_in[p + 8];
    float* out = (float*)d_out;

    cudaFuncSetAttribute(k_main, cudaFuncAttributeMaxDynamicSharedMemorySize, SMEM_TOTAL);

    k_prep_all<<<320, 256>>>(s_mask, nw, pt_w, pe_w1, pe_b1, pe_w2, pe_b2);
    k_main<<<NBLK, 256, SMEM_TOTAL>>>(student_emb, s_mask, t_mask,
                                      pt_b, ln_g, ln_b, out);
}

// round 14
// speedup vs baseline: 1.2512x; 1.0340x over previous
#include <cuda_runtime.h>
#include <cuda_fp16.h>
#include <cstdint>

#define B_   32
#define S_   4096
#define T_   8192
#define DIN  128
#define DT   256
#define M_   (B_ * T_)        // 262144
#define TILE_M 64
#define NBLK  (M_ / TILE_M)   // 4096

// ---------------- device-global tables (no runtime allocation) -------------
__device__ float    g_slens[B_];
__device__ float    g_w[4];
__device__ uint16_t g_wh[DT * DT];      // W fp16 (rounded), [k][n] row-major
__device__ uint32_t g_peh[T_ * 64];     // pos_emb packed fp16x2, [t][pair] (256B/row)

// ---------------- smem layout (swizzled, pitch 512) ------------------------
#define OFF_A    0              // 64 rows x 512 B (fp16: 256 cols)
#define OFF_B0   32768
#define B_STAGE  16384          // 32 k-rows x 512 B (one K32 chunk)
#define OFF_PRM  (OFF_B0 + 4 * B_STAGE)     // 98304: bias/g/beta, 3 KB
#define SMEM_TOTAL (OFF_PRM + 3072)         // 101376 -> 2 CTAs/SM
// epilogue overlays (valid after final mainloop barrier; pipeline drained):
#define OFF_PS   OFF_B0
#define OFF_PS2  (OFF_B0 + 1024)

// ---------------- asm helpers ----------------------------------------------
__device__ __forceinline__ uint32_t smem_u32(const void* p) {
    uint32_t a;
    asm("{ .reg .u64 t; cvta.to.shared.u64 t, %1; cvt.u32.u64 %0, t; }" : "=r"(a) : "l"(p));
    return a;
}
#define CP_ASYNC16(dst, src) \
    asm volatile("cp.async.cg.shared.global [%0], [%1], 16;" :: "r"(dst), "l"(src))
#define CP_COMMIT() asm volatile("cp.async.commit_group;" ::: "memory")
#define CP_WAIT0()  asm volatile("cp.async.wait_group 0;" ::: "memory")
#define CP_WAIT1()  asm volatile("cp.async.wait_group 1;" ::: "memory")
#define CP_WAIT2()  asm volatile("cp.async.wait_group 2;" ::: "memory")

#define LDSM4(r, addr) \
    asm volatile("ldmatrix.sync.aligned.m8n8.x4.shared.b16 {%0,%1,%2,%3}, [%4];" \
        : "=r"((r)[0]), "=r"((r)[1]), "=r"((r)[2]), "=r"((r)[3]) : "r"(addr))
#define LDSM4T(r, addr) \
    asm volatile("ldmatrix.sync.aligned.m8n8.x4.trans.shared.b16 {%0,%1,%2,%3}, [%4];" \
        : "=r"((r)[0]), "=r"((r)[1]), "=r"((r)[2]), "=r"((r)[3]) : "r"(addr))

// NOTE: not volatile -> ptxas is free to schedule/pipeline MMAs.
__device__ __forceinline__ void mma_f16(float* c, const uint32_t* a, const uint32_t* b) {
    asm("mma.sync.aligned.m16n8k16.row.col.f32.f16.f16.f32 "
        "{%0,%1,%2,%3}, {%4,%5,%6,%7}, {%8,%9}, {%0,%1,%2,%3};"
        : "+f"(c[0]), "+f"(c[1]), "+f"(c[2]), "+f"(c[3])
        : "r"(a[0]), "r"(a[1]), "r"(a[2]), "r"(a[3]), "r"(b[0]), "r"(b[1]));
}

__device__ __forceinline__ uint32_t h2u(__half2 h) {
    uint32_t u; *(__half2*)&u = h; return u;
}

__device__ __forceinline__ float gelu_exact(float x) {
    return 0.5f * x * (1.0f + erff(x * 0.70710678118654752440f));
}

// ---------------- fused prep kernel ----------------------------------------
// blocks 0..255   : pos_emb table (32 t-rows each; w2 col in REGISTERS)
// blocks 256..287 : s_lens (one batch row each); block 256 also softmax(nw)
// blocks 288..319 : W -> fp16 (2048 elements each)
__global__ void __launch_bounds__(256)
k_prep_all(const float* __restrict__ s_mask, const float* __restrict__ nw,
           const float* __restrict__ W,
           const float* __restrict__ w1, const float* __restrict__ b1,
           const float* __restrict__ w2, const float* __restrict__ b2) {
    __shared__ float2 w2s[64 * 64];      // 32 KB
    __shared__ float  hs[32][64];        // 8 KB
    int tid = threadIdx.x;
    int blk = blockIdx.x;

    if (blk < 256) {
        // ---- pos_emb ----
        int t0b = blk * 32;
        const float step = 1.0f / (float)(T_ - 1);
        const float2* w2v = (const float2*)w2;
        #pragma unroll
        for (int i = 0; i < 16; i++) w2s[tid + 256 * i] = w2v[tid + 256 * i];
        #pragma unroll
        for (int i = 0; i < 8; i++) {
            int idx = tid + 256 * i;
            int tt = idx >> 6, j = idx & 63;
            float pos = (float)(t0b + tt) * step;
            hs[tt][j] = gelu_exact(pos * w1[j] + b1[j]);
        }
        __syncthreads();
        int dp = tid & 63, tg = tid >> 6;
        float a0[8], a1[8];
        {
            float b2a = b2[2 * dp], b2b = b2[2 * dp + 1];
            #pragma unroll
            for (int p = 0; p < 8; p++) { a0[p] = b2a; a1[p] = b2b; }
        }
        // w2 column in registers, read smem ONCE (two halves of 32 float2)
        #pragma unroll
        for (int half = 0; half < 2; half++) {
            float2 wreg[32];
            #pragma unroll
            for (int j = 0; j < 32; j++) wreg[j] = w2s[(half * 32 + j) * 64 + dp];
            #pragma unroll
            for (int p = 0; p < 8; p++) {
                int tt = tg + 4 * p;
                float s0 = a0[p], s1 = a1[p];
                #pragma unroll
                for (int j = 0; j < 32; j++) {
                    float hv = hs[tt][half * 32 + j];
                    s0 = fmaf(hv, wreg[j].x, s0);
                    s1 = fmaf(hv, wreg[j].y, s1);
                }
                a0[p] = s0; a1[p] = s1;
            }
        }
        #pragma unroll
        for (int p = 0; p < 8; p++) {
            int tt = tg + 4 * p;
            g_peh[(size_t)(t0b + tt) * 64 + dp] = h2u(__floats2half2_rn(a0[p], a1[p]));
        }
    } else if (blk < 288) {
        // ---- s_lens ----
        int bb = blk - 256;
        float* part = (float*)w2s;
        int w = tid >> 5, lane = tid & 31;
        const float* row = s_mask + (size_t)bb * S_;
        float s = 0.f;
        #pragma unroll 4
        for (int i = tid; i < S_; i += 256) s += row[i];
        #pragma unroll
        for (int o = 16; o; o >>= 1) s += __shfl_xor_sync(0xFFFFFFFFu, s, o);
        if (lane == 0) part[w] = s;
        __syncthreads();
        if (tid == 0) {
            float t = 0.f;
            #pragma unroll
            for (int i = 0; i < 8; i++) t += part[i];
            g_slens[bb] = t;
            if (bb == 0) {
                float a = nw[0], b = nw[1], c = nw[2];
                float m = fmaxf(a, fmaxf(b, c));
                float ea = expf(a - m), eb = expf(b - m), ec = expf(c - m);
                float inv = 1.f / (ea + eb + ec);
                g_w[0] = ea * inv; g_w[1] = eb * inv; g_w[2] = ec * inv;
            }
        }
    } else {
        // ---- W -> fp16 ----
        int base = (blk - 288) * 2048;
        #pragma unroll
        for (int i = 0; i < 8; i++) {
            int idx = base + tid + 256 * i;
            __half h = __float2half_rn(W[idx]);
            g_wh[idx] = *(uint16_t*)&h;
        }
    }
}

// ---------------- B chunk loader: K=32, swizzled, cp.async (16KB) ----------
__device__ __forceinline__ void load_B_chunk(uint32_t sb, int stage, int chunk, int tid) {
    uint32_t dst = sb + OFF_B0 + stage * B_STAGE;
    const char* src0 = (const char*)(g_wh + chunk * 32 * DT);
    #pragma unroll
    for (int i = 0; i < 4; i++) {
        int f = tid + 256 * i;             // 0..1023
        int r = f >> 5;                    // K row within chunk (0..31)
        int c = f & 31;                    // 16B segment
        CP_ASYNC16(dst + r * 512 + ((c ^ (r & 7)) << 4), src0 + (size_t)r * 512 + c * 16);
    }
}

// ---------------- main kernel: fused gather + fp16 GEMM + epilogue ---------
__global__ void __launch_bounds__(256, 2)
k_main(const float* __restrict__ emb, const float* __restrict__ s_mask,
       const float* __restrict__ tmask,
       const float* __restrict__ bias, const float* __restrict__ lng,
       const float* __restrict__ lnb, float* __restrict__ out) {
    extern __shared__ char smem[];
    uint32_t sb = smem_u32(smem);
    int tid = threadIdx.x, wid = tid >> 5, lane = tid & 31;
    int wm = wid >> 2;        // 0..1 : M half (32 rows)
    int wn = wid & 3;         // 0..3 : N quarter (64 cols)
    int m0 = blockIdx.x * TILE_M;
    int t0 = m0 & (T_ - 1);   // all 64 rows share batch b
    int b  = m0 >> 13;

    // early exit: t_mask is a prefix mask -> whole block exactly zero.
    if (tmask[m0] == 0.f) {
        float4 z = make_float4(0.f, 0.f, 0.f, 0.f);
        float4* o4 = (float4*)(out + (size_t)m0 * DT);
        #pragma unroll
        for (int i = 0; i < 16; i++) o4[tid + 256 * i] = z;
        return;
    }

    // group 0: B chunk 0 + pos_emb half of A + epilogue params
    load_B_chunk(sb, 0, 0, tid);
    {
        #pragma unroll
        for (int i = 0; i < 4; i++) {
            int f = tid + 256 * i;         // 0..1023
            int row = f >> 4;              // 0..63
            int seg = f & 15;              // 16B segment within 256B
            uint32_t byte = (uint32_t)(256 + seg * 16) ^ ((row & 7) << 4);
            CP_ASYNC16(sb + OFF_A + row * 512 + byte,
                       (const char*)(g_peh + (size_t)(t0 + row) * 64 + seg * 4));
        }
        if (tid < 192) {
            int which = tid >> 6;          // 0..2
            int seg   = tid & 63;          // 16B segment
            const float* src = (which == 0) ? bias : (which == 1) ? lng : lnb;
            CP_ASYNC16(sb + OFF_PRM + which * 1024 + seg * 16, (const char*)(src + seg * 4));
        }
    }
    CP_COMMIT();
    // groups 1,2: B chunks 1,2
    load_B_chunk(sb, 1, 1, tid);
    CP_COMMIT();
    load_B_chunk(sb, 2, 2, tid);
    CP_COMMIT();

    // ---- produce blended half of A tile (64 x 128) as fp16, swizzled ------
    {
        float slen = g_slens[b];
        float wv0 = g_w[0], wv1 = g_w[1], wv2 = g_w[2];
        const float* mrow = s_mask + (size_t)b * S_;
        int   ip[8], ic[8], in_[8];
        float w0a[8], w1a[8], w2a[8];
        #pragma unroll
        for (int i = 0; i < 8; i++) {
            int t = t0 + wid * 8 + i;
            float pos = (float)t * (1.0f / (float)(T_ - 1));
            float sp  = pos * (slen - 1.0f);
            int curr = (int)sp;
            ip[i] = max(curr - 1, 0);
            ic[i] = curr;
            in_[i] = min(curr + 1, S_ - 1);
        }
        #pragma unroll
        for (int i = 0; i < 8; i++) {
            w0a[i] = wv0 * mrow[ip[i]];
            w1a[i] = wv1 * mrow[ic[i]];
            w2a[i] = wv2 * mrow[in_[i]];
        }
        #pragma unroll 2
        for (int i = 0; i < 8; i++) {
            int row = wid * 8 + i;
            const float4* ep = (const float4*)(emb + ((size_t)b * S_ + ip[i]) * DIN);
            const float4* ec = (const float4*)(emb + ((size_t)b * S_ + ic[i]) * DIN);
            const float4* en = (const float4*)(emb + ((size_t)b * S_ + in_[i]) * DIN);
            float4 vp = ep[lane], vc = ec[lane], vn = en[lane];
            float w0 = w0a[i], w1 = w1a[i], w2 = w2a[i];
            float v0 = w0 * vp.x + w1 * vc.x + w2 * vn.x;
            float v1 = w0 * vp.y + w1 * vc.y + w2 * vn.y;
            float v2 = w0 * vp.z + w1 * vc.z + w2 * vn.z;
            float v3 = w0 * vp.w + w1 * vc.w + w2 * vn.w;
            __half2 hh0 = __floats2half2_rn(v0, v1);
            __half2 hh1 = __floats2half2_rn(v2, v3);
            uint32_t rbase = row * 512;
            uint32_t o1 = rbase + ((8 * lane) ^ ((row & 7) << 4));
            *(uint2*)(smem + OFF_A + o1) = make_uint2(h2u(hh0), h2u(hh1));
        }
    }

    // ---- ldmatrix lane addressing ----
    int xr = (lane & 7) + ((lane >> 3) & 1) * 8;   // 0..15
    int xg = lane >> 4;                            // 0..1
    int a_row = wm * 32 + xr;
    uint32_t a_base = sb + OFF_A + a_row * 512;
    uint32_t a_xor  = ((a_row & 7) << 4) ^ (xg * 16);
    uint32_t b_base = xr * 512;
    uint32_t b_xor  = (xr & 7) << 4;
    int b_col = wn * 128 + xg * 16;
    uint32_t co[4];
    #pragma unroll
    for (int p = 0; p < 4; p++) co[p] = ((uint32_t)(b_col + p * 32) ^ b_xor) + b_base;

    float acc[2][8][4];
    #pragma unroll
    for (int mt = 0; mt < 2; mt++)
        #pragma unroll
        for (int nt = 0; nt < 8; nt++)
            #pragma unroll
            for (int c = 0; c < 4; c++) acc[mt][nt][c] = 0.f;

    // ---- mainloop: 8 chunks of K=32, 4-stage ring (prefetch distance 3) ---
    for (int kc = 0; kc < 8; kc++) {
        if (kc <= 5) { CP_WAIT2(); } else if (kc == 6) { CP_WAIT1(); } else { CP_WAIT0(); }
        __syncthreads();
        if (kc < 5) {
            load_B_chunk(sb, (kc + 3) & 3, kc + 3, tid);
            CP_COMMIT();
        }
        uint32_t bstage = sb + OFF_B0 + (kc & 3) * B_STAGE;
        #pragma unroll
        for (int kk = 0; kk < 2; kk++) {
            uint32_t aoff = ((uint32_t)(kc * 64 + kk * 32)) ^ a_xor;
            uint32_t A0[4], A1[4];
            LDSM4(A0, a_base + aoff);
            LDSM4(A1, a_base + 16 * 512 + aoff);
            uint32_t bk = bstage + kk * 16 * 512;
            #pragma unroll
            for (int p = 0; p < 4; p++) {
                uint32_t Bf[4];
                LDSM4T(Bf, bk + co[p]);
                mma_f16(acc[0][2 * p],     A0, &Bf[0]);
                mma_f16(acc[0][2 * p + 1], A0, &Bf[2]);
                mma_f16(acc[1][2 * p],     A1, &Bf[0]);
                mma_f16(acc[1][2 * p + 1], A1, &Bf[2]);
            }
        }
    }
    __syncthreads();   // pipeline drained -> B region free for LN overlay

    // ---- epilogue: gelu + layernorm + mask (params from smem) -------------
    float* ps   = (float*)(smem + OFF_PS);
    float* ps2  = (float*)(smem + OFF_PS2);
    const float* smB  = (const float*)(smem + OFF_PRM);
    const float* smG  = (const float*)(smem + OFF_PRM + 1024);
    const float* smBe = (const float*)(smem + OFF_PRM + 2048);

    // hoist mask loads (hide L2 latency behind the reduction phase)
    float mk[2][2];
    #pragma unroll
    for (int mt = 0; mt < 2; mt++) {
        int rA = wm * 32 + mt * 16 + (lane >> 2);
        mk[mt][0] = tmask[m0 + rA];
        mk[mt][1] = tmask[m0 + rA + 8];
    }

    float2 bia[8], gg[8], be[8];
    #pragma unroll
    for (int nt = 0; nt < 8; nt++) {
        int c = wn * 64 + nt * 8 + 2 * (lane & 3);
        bia[nt] = *(const float2*)&smB[c];
        gg[nt]  = *(const float2*)&smG[c];
        be[nt]  = *(const float2*)&smBe[c];
    }

    #pragma unroll
    for (int mt = 0; mt < 2; mt++) {
        float sA = 0.f, s2A = 0.f, sB = 0.f, s2B = 0.f;
        #pragma unroll
        for (int nt = 0; nt < 8; nt++) {
            float v0 = gelu_exact(acc[mt][nt][0] + bia[nt].x);
            float v1 = gelu_exact(acc[mt][nt][1] + bia[nt].y);
            float v2 = gelu_exact(acc[mt][nt][2] + bia[nt].x);
            float v3 = gelu_exact(acc[mt][nt][3] + bia[nt].y);
            acc[mt][nt][0] = v0; acc[mt][nt][1] = v1;
            acc[mt][nt][2] = v2; acc[mt][nt][3] = v3;
            sA += v0 + v1; s2A += v0 * v0 + v1 * v1;
            sB += v2 + v3; s2B += v2 * v2 + v3 * v3;
        }
        #pragma unroll
        for (int o = 1; o <= 2; o <<= 1) {
            sA  += __shfl_xor_sync(0xFFFFFFFFu, sA,  o);
            s2A += __shfl_xor_sync(0xFFFFFFFFu, s2A, o);
            sB  += __shfl_xor_sync(0xFFFFFFFFu, sB,  o);
            s2B += __shfl_xor_sync(0xFFFFFFFFu, s2B, o);
        }
        if ((lane & 3) == 0) {
            int rA = wm * 32 + mt * 16 + (lane >> 2);
            ps[rA * 4 + wn]  = sA;  ps2[rA * 4 + wn]  = s2A;
            ps[(rA + 8) * 4 + wn] = sB; ps2[(rA + 8) * 4 + wn] = s2B;
        }
    }
    __syncthreads();

    #pragma unroll
    for (int mt = 0; mt < 2; mt++) {
        int rA = wm * 32 + mt * 16 + (lane >> 2);
        int rB = rA + 8;
        float tsA  = ps[rA * 4] + ps[rA * 4 + 1] + ps[rA * 4 + 2] + ps[rA * 4 + 3];
        float ts2A = ps2[rA * 4] + ps2[rA * 4 + 1] + ps2[rA * 4 + 2] + ps2[rA * 4 + 3];
        float tsB  = ps[rB * 4] + ps[rB * 4 + 1] + ps[rB * 4 + 2] + ps[rB * 4 + 3];
        float ts2B = ps2[rB * 4] + ps2[rB * 4 + 1] + ps2[rB * 4 + 2] + ps2[rB * 4 + 3];
        float muA = tsA * (1.f / 256.f);
        float muB = tsB * (1.f / 256.f);
        float invA = rsqrtf(ts2A * (1.f / 256.f) - muA * muA + 1e-5f);
        float invB = rsqrtf(ts2B * (1.f / 256.f) - muB * muB + 1e-5f);
        float mkA = mk[mt][0];
        float mkB = mk[mt][1];
        #pragma unroll
        for (int nt = 0; nt < 8; nt++) {
            int c = wn * 64 + nt * 8 + 2 * (lane & 3);
            float2 o1, o2;
            o1.x = ((acc[mt][nt][0] - muA) * invA * gg[nt].x + be[nt].x) * mkA;
            o1.y = ((acc[mt][nt][1] - muA) * invA * gg[nt].y + be[nt].y) * mkA;
            o2.x = ((acc[mt][nt][2] - muB) * invB * gg[nt].x + be[nt].x) * mkB;
            o2.y = ((acc[mt][nt][3] - muB) * invB * gg[nt].y + be[nt].y) * mkB;
            *(float2*)(out + (size_t)(m0 + rA) * DT + c) = o1;
            *(float2*)(out + (size_t)(m0 + rB) * DT + c) = o2;
        }
    }
}

// ---------------- launch ---------------------------------------------------
extern "C" void kernel_launch(void* const* d_in, const int* in_sizes, int n_in,
                              void* d_out, int out_size) {
    const float* student_emb = (const float*)d_in[0];
    const float* s_mask      = (const float*)d_in[1];
    const float* t_mask      = (const float*)d_in[2];
    int p = (in_sizes[3] == 64) ? 3 : 4;
    const float* pe_w1 = (const float*)d_in[p + 0];
    const float* pe_b1 = (const float*)d_in[p + 1];
    const float* pe_w2 = (const float*)d_in[p + 2];
    const float* pe_b2 = (const float*)d_in[p + 3];
    const float* pt_w  = (const float*)d_in[p + 4];
    const float* pt_b  = (const float*)d_in[p + 5];
    const float* ln_g  = (const float*)d_in[p + 6];
    const float* ln_b  = (const float*)d_in[p + 7];
    const float* nw    = (const float*)d_in[p + 8];
    float* out = (float*)d_out;

    cudaFuncSetAttribute(k_main, cudaFuncAttributeMaxDynamicSharedMemorySize, SMEM_TOTAL);

    k_prep_all<<<320, 256>>>(s_mask, nw, pt_w, pe_w1, pe_b1, pe_w2, pe_b2);
    k_main<<<NBLK, 256, SMEM_TOTAL>>>(student_emb, s_mask, t_mask,
                                      pt_b, ln_g, ln_b, out);
}

// round 15
// speedup vs baseline: 1.2669x; 1.0125x over previous
#include <cuda_runtime.h>
#include <cuda_fp16.h>
#include <cstdint>

#define B_   32
#define S_   4096
#define T_   8192
#define DIN  128
#define DT   256
#define M_   (B_ * T_)        // 262144
#define TILE_M 64
#define NBLK  (M_ / TILE_M)   // 4096

// ---------------- device-global tables (no runtime allocation) -------------
__device__ float    g_slens[B_];
__device__ float    g_w[4];
__device__ uint16_t g_wh[DT * DT];      // W fp16 (rounded), [k][n] row-major
__device__ uint32_t g_peh[T_ * 64];     // pos_emb packed fp16x2, [t][pair] (256B/row)

// ---------------- smem layout (swizzled, pitch 512) ------------------------
#define OFF_A    0              // 64 rows x 512 B (fp16: 256 cols)
#define OFF_B0   32768
#define B_STAGE  16384          // 32 k-rows x 512 B (one K32 chunk)
#define OFF_PRM  (OFF_B0 + 3 * B_STAGE)     // 81920: bias/g/beta, 3 KB
#define SMEM_TOTAL (OFF_PRM + 3072)         // 84992 -> 2 CTAs/SM
// epilogue overlays (valid after final mainloop barrier; pipeline drained):
#define OFF_PS   OFF_B0
#define OFF_PS2  (OFF_B0 + 1024)

// ---------------- asm helpers ----------------------------------------------
__device__ __forceinline__ uint32_t smem_u32(const void* p) {
    uint32_t a;
    asm("{ .reg .u64 t; cvta.to.shared.u64 t, %1; cvt.u32.u64 %0, t; }" : "=r"(a) : "l"(p));
    return a;
}
#define CP_ASYNC16(dst, src) \
    asm volatile("cp.async.cg.shared.global [%0], [%1], 16;" :: "r"(dst), "l"(src))
#define CP_COMMIT() asm volatile("cp.async.commit_group;" ::: "memory")
#define CP_WAIT0()  asm volatile("cp.async.wait_group 0;" ::: "memory")
#define CP_WAIT1()  asm volatile("cp.async.wait_group 1;" ::: "memory")

#define LDSM4(r, addr) \
    asm volatile("ldmatrix.sync.aligned.m8n8.x4.shared.b16 {%0,%1,%2,%3}, [%4];" \
        : "=r"((r)[0]), "=r"((r)[1]), "=r"((r)[2]), "=r"((r)[3]) : "r"(addr))
#define LDSM4T(r, addr) \
    asm volatile("ldmatrix.sync.aligned.m8n8.x4.trans.shared.b16 {%0,%1,%2,%3}, [%4];" \
        : "=r"((r)[0]), "=r"((r)[1]), "=r"((r)[2]), "=r"((r)[3]) : "r"(addr))

// NOTE: not volatile -> ptxas is free to schedule/pipeline MMAs.
__device__ __forceinline__ void mma_f16(float* c, const uint32_t* a, const uint32_t* b) {
    asm("mma.sync.aligned.m16n8k16.row.col.f32.f16.f16.f32 "
        "{%0,%1,%2,%3}, {%4,%5,%6,%7}, {%8,%9}, {%0,%1,%2,%3};"
        : "+f"(c[0]), "+f"(c[1]), "+f"(c[2]), "+f"(c[3])
        : "r"(a[0]), "r"(a[1]), "r"(a[2]), "r"(a[3]), "r"(b[0]), "r"(b[1]));
}

__device__ __forceinline__ uint32_t h2u(__half2 h) {
    uint32_t u; *(__half2*)&u = h; return u;
}

__device__ __forceinline__ float gelu_exact(float x) {
    return 0.5f * x * (1.0f + erff(x * 0.70710678118654752440f));
}

// ---------------- fused prep kernel ----------------------------------------
// blocks 0..255   : pos_emb table (32 t-rows each; w2 col in REGISTERS)
// blocks 256..287 : s_lens (one batch row each); block 256 also softmax(nw)
// blocks 288..319 : W -> fp16 (2048 elements each)
__global__ void __launch_bounds__(256)
k_prep_all(const float* __restrict__ s_mask, const float* __restrict__ nw,
           const float* __restrict__ W,
           const float* __restrict__ w1, const float* __restrict__ b1,
           const float* __restrict__ w2, const float* __restrict__ b2) {
    __shared__ float2 w2s[64 * 64];      // 32 KB
    __shared__ float  hs[32][64];        // 8 KB
    int tid = threadIdx.x;
    int blk = blockIdx.x;

    if (blk < 256) {
        // ---- pos_emb ----
        int t0b = blk * 32;
        const float step = 1.0f / (float)(T_ - 1);
        const float2* w2v = (const float2*)w2;
        #pragma unroll
        for (int i = 0; i < 16; i++) w2s[tid + 256 * i] = w2v[tid + 256 * i];
        #pragma unroll
        for (int i = 0; i < 8; i++) {
            int idx = tid + 256 * i;
            int tt = idx >> 6, j = idx & 63;
            float pos = (float)(t0b + tt) * step;
            hs[tt][j] = gelu_exact(pos * w1[j] + b1[j]);
        }
        __syncthreads();
        int dp = tid & 63, tg = tid >> 6;
        float a0[8], a1[8];
        {
            float b2a = b2[2 * dp], b2b = b2[2 * dp + 1];
            #pragma unroll
            for (int p = 0; p < 8; p++) { a0[p] = b2a; a1[p] = b2b; }
        }
        // w2 column in registers, read smem ONCE (two halves of 32 float2)
        #pragma unroll
        for (int half = 0; half < 2; half++) {
            float2 wreg[32];
            #pragma unroll
            for (int j = 0; j < 32; j++) wreg[j] = w2s[(half * 32 + j) * 64 + dp];
            #pragma unroll
            for (int p = 0; p < 8; p++) {
                int tt = tg + 4 * p;
                float s0 = a0[p], s1 = a1[p];
                #pragma unroll
                for (int j = 0; j < 32; j++) {
                    float hv = hs[tt][half * 32 + j];
                    s0 = fmaf(hv, wreg[j].x, s0);
                    s1 = fmaf(hv, wreg[j].y, s1);
                }
                a0[p] = s0; a1[p] = s1;
            }
        }
        #pragma unroll
        for (int p = 0; p < 8; p++) {
            int tt = tg + 4 * p;
            g_peh[(size_t)(t0b + tt) * 64 + dp] = h2u(__floats2half2_rn(a0[p], a1[p]));
        }
    } else if (blk < 288) {
        // ---- s_lens ----
        int bb = blk - 256;
        float* part = (float*)w2s;
        int w = tid >> 5, lane = tid & 31;
        const float* row = s_mask + (size_t)bb * S_;
        float s = 0.f;
        #pragma unroll 4
        for (int i = tid; i < S_; i += 256) s += row[i];
        #pragma unroll
        for (int o = 16; o; o >>= 1) s += __shfl_xor_sync(0xFFFFFFFFu, s, o);
        if (lane == 0) part[w] = s;
        __syncthreads();
        if (tid == 0) {
            float t = 0.f;
            #pragma unroll
            for (int i = 0; i < 8; i++) t += part[i];
            g_slens[bb] = t;
            if (bb == 0) {
                float a = nw[0], b = nw[1], c = nw[2];
                float m = fmaxf(a, fmaxf(b, c));
                float ea = expf(a - m), eb = expf(b - m), ec = expf(c - m);
                float inv = 1.f / (ea + eb + ec);
                g_w[0] = ea * inv; g_w[1] = eb * inv; g_w[2] = ec * inv;
            }
        }
    } else {
        // ---- W -> fp16 ----
        int base = (blk - 288) * 2048;
        #pragma unroll
        for (int i = 0; i < 8; i++) {
            int idx = base + tid + 256 * i;
            __half h = __float2half_rn(W[idx]);
            g_wh[idx] = *(uint16_t*)&h;
        }
    }
}

// ---------------- B chunk loader: K=32, swizzled, cp.async (16KB) ----------
__device__ __forceinline__ void load_B_chunk(uint32_t sb, int stage, int chunk, int tid) {
    uint32_t dst = sb + OFF_B0 + stage * B_STAGE;
    const char* src0 = (const char*)(g_wh + chunk * 32 * DT);
    #pragma unroll
    for (int i = 0; i < 4; i++) {
        int f = tid + 256 * i;             // 0..1023
        int r = f >> 5;                    // K row within chunk (0..31)
        int c = f & 31;                    // 16B segment
        CP_ASYNC16(dst + r * 512 + ((c ^ (r & 7)) << 4), src0 + (size_t)r * 512 + c * 16);
    }
}

// ---------------- main kernel: fused gather + fp16 GEMM + epilogue ---------
__global__ void __launch_bounds__(256, 2)
k_main(const float* __restrict__ emb, const float* __restrict__ s_mask,
       const float* __restrict__ tmask,
       const float* __restrict__ bias, const float* __restrict__ lng,
       const float* __restrict__ lnb, float* __restrict__ out) {
    extern __shared__ char smem[];
    uint32_t sb = smem_u32(smem);
    int tid = threadIdx.x, wid = tid >> 5, lane = tid & 31;
    int wm = wid >> 2;        // 0..1 : M half (32 rows)
    int wn = wid & 3;         // 0..3 : N quarter (64 cols)
    int m0 = blockIdx.x * TILE_M;
    int t0 = m0 & (T_ - 1);   // all 64 rows share batch b
    int b  = m0 >> 13;

    // issue these loads early: they head the A-prod dependency chain
    float slen = g_slens[b];
    float wv0 = g_w[0], wv1 = g_w[1], wv2 = g_w[2];

    // early exit: t_mask is a prefix mask -> whole block exactly zero.
    if (tmask[m0] == 0.f) {
        float4 z = make_float4(0.f, 0.f, 0.f, 0.f);
        float4* o4 = (float4*)(out + (size_t)m0 * DT);
        #pragma unroll
        for (int i = 0; i < 16; i++) o4[tid + 256 * i] = z;
        return;
    }

    // group 0: B chunk 0 + pos_emb half of A + epilogue params
    load_B_chunk(sb, 0, 0, tid);
    {
        #pragma unroll
        for (int i = 0; i < 4; i++) {
            int f = tid + 256 * i;         // 0..1023
            int row = f >> 4;              // 0..63
            int seg = f & 15;              // 16B segment within 256B
            uint32_t byte = (uint32_t)(256 + seg * 16) ^ ((row & 7) << 4);
            CP_ASYNC16(sb + OFF_A + row * 512 + byte,
                       (const char*)(g_peh + (size_t)(t0 + row) * 64 + seg * 4));
        }
        if (tid < 192) {
            int which = tid >> 6;          // 0..2
            int seg   = tid & 63;          // 16B segment
            const float* src = (which == 0) ? bias : (which == 1) ? lng : lnb;
            CP_ASYNC16(sb + OFF_PRM + which * 1024 + seg * 16, (const char*)(src + seg * 4));
        }
    }
    CP_COMMIT();
    // group 1: B chunk 1
    load_B_chunk(sb, 1, 1, tid);
    CP_COMMIT();

    // ---- produce blended half of A tile (64 x 128) as fp16, swizzled ------
    {
        const float* mrow = s_mask + (size_t)b * S_;
        int   ip[8], ic[8], in_[8];
        float w0a[8], w1a[8], w2a[8];
        #pragma unroll
        for (int i = 0; i < 8; i++) {
            int t = t0 + wid * 8 + i;
            float pos = (float)t * (1.0f / (float)(T_ - 1));
            float sp  = pos * (slen - 1.0f);
            int curr = (int)sp;
            ip[i] = max(curr - 1, 0);
            ic[i] = curr;
            in_[i] = min(curr + 1, S_ - 1);
        }
        #pragma unroll
        for (int i = 0; i < 8; i++) {
            w0a[i] = wv0 * mrow[ip[i]];
            w1a[i] = wv1 * mrow[ic[i]];
            w2a[i] = wv2 * mrow[in_[i]];
        }
        #pragma unroll 2
        for (int i = 0; i < 8; i++) {
            int row = wid * 8 + i;
            const float4* ep = (const float4*)(emb + ((size_t)b * S_ + ip[i]) * DIN);
            const float4* ec = (const float4*)(emb + ((size_t)b * S_ + ic[i]) * DIN);
            const float4* en = (const float4*)(emb + ((size_t)b * S_ + in_[i]) * DIN);
            float4 vp = ep[lane], vc = ec[lane], vn = en[lane];
            float w0 = w0a[i], w1 = w1a[i], w2 = w2a[i];
            float v0 = w0 * vp.x + w1 * vc.x + w2 * vn.x;
            float v1 = w0 * vp.y + w1 * vc.y + w2 * vn.y;
            float v2 = w0 * vp.z + w1 * vc.z + w2 * vn.z;
            float v3 = w0 * vp.w + w1 * vc.w + w2 * vn.w;
            __half2 hh0 = __floats2half2_rn(v0, v1);
            __half2 hh1 = __floats2half2_rn(v2, v3);
            uint32_t rbase = row * 512;
            uint32_t o1 = rbase + ((8 * lane) ^ ((row & 7) << 4));
            *(uint2*)(smem + OFF_A + o1) = make_uint2(h2u(hh0), h2u(hh1));
        }
    }

    // ---- ldmatrix lane addressing ----
    int xr = (lane & 7) + ((lane >> 3) & 1) * 8;   // 0..15
    int xg = lane >> 4;                            // 0..1
    int a_row = wm * 32 + xr;
    uint32_t a_base = sb + OFF_A + a_row * 512;
    uint32_t a_xor  = ((a_row & 7) << 4) ^ (xg * 16);
    uint32_t b_base = xr * 512;
    uint32_t b_xor  = (xr & 7) << 4;
    int b_col = wn * 128 + xg * 16;
    uint32_t co[4];
    #pragma unroll
    for (int p = 0; p < 4; p++) co[p] = ((uint32_t)(b_col + p * 32) ^ b_xor) + b_base;

    float acc[2][8][4];
    #pragma unroll
    for (int mt = 0; mt < 2; mt++)
        #pragma unroll
        for (int nt = 0; nt < 8; nt++)
            #pragma unroll
            for (int c = 0; c < 4; c++) acc[mt][nt][c] = 0.f;

    // ---- mainloop: 8 chunks of K=32, 3-stage pipeline ---------------------
    int st = 0;
    for (int kc = 0; kc < 8; kc++) {
        if (kc == 7) { CP_WAIT0(); } else { CP_WAIT1(); }
        __syncthreads();
        if (kc < 6) {
            int nst = st + 2; if (nst >= 3) nst -= 3;
            load_B_chunk(sb, nst, kc + 2, tid);
            CP_COMMIT();
        }
        uint32_t bstage = sb + OFF_B0 + st * B_STAGE;
        #pragma unroll
        for (int kk = 0; kk < 2; kk++) {
            uint32_t aoff = ((uint32_t)(kc * 64 + kk * 32)) ^ a_xor;
            uint32_t A0[4], A1[4];
            LDSM4(A0, a_base + aoff);
            LDSM4(A1, a_base + 16 * 512 + aoff);
            uint32_t bk = bstage + kk * 16 * 512;
            #pragma unroll
            for (int p = 0; p < 4; p++) {
                uint32_t Bf[4];
                LDSM4T(Bf, bk + co[p]);
                mma_f16(acc[0][2 * p],     A0, &Bf[0]);
                mma_f16(acc[0][2 * p + 1], A0, &Bf[2]);
                mma_f16(acc[1][2 * p],     A1, &Bf[0]);
                mma_f16(acc[1][2 * p + 1], A1, &Bf[2]);
            }
        }
        st = (st == 2) ? 0 : st + 1;
    }
    __syncthreads();   // pipeline drained -> B region free for LN overlay

    // ---- epilogue: gelu + layernorm + mask (params from smem) -------------
    float* ps   = (float*)(smem + OFF_PS);
    float* ps2  = (float*)(smem + OFF_PS2);
    const float* smB  = (const float*)(smem + OFF_PRM);
    const float* smG  = (const float*)(smem + OFF_PRM + 1024);
    const float* smBe = (const float*)(smem + OFF_PRM + 2048);

    // hoist mask loads (hide L2 latency behind the reduction phase)
    float mk[2][2];
    #pragma unroll
    for (int mt = 0; mt < 2; mt++) {
        int rA = wm * 32 + mt * 16 + (lane >> 2);
        mk[mt][0] = tmask[m0 + rA];
        mk[mt][1] = tmask[m0 + rA + 8];
    }

    float2 bia[8], gg[8], be[8];
    #pragma unroll
    for (int nt = 0; nt < 8; nt++) {
        int c = wn * 64 + nt * 8 + 2 * (lane & 3);
        bia[nt] = *(const float2*)&smB[c];
        gg[nt]  = *(const float2*)&smG[c];
        be[nt]  = *(const float2*)&smBe[c];
    }

    #pragma unroll
    for (int mt = 0; mt < 2; mt++) {
        float sA = 0.f, s2A = 0.f, sB = 0.f, s2B = 0.f;
        #pragma unroll
        for (int nt = 0; nt < 8; nt++) {
            float v0 = gelu_exact(acc[mt][nt][0] + bia[nt].x);
            float v1 = gelu_exact(acc[mt][nt][1] + bia[nt].y);
            float v2 = gelu_exact(acc[mt][nt][2] + bia[nt].x);
            float v3 = gelu_exact(acc[mt][nt][3] + bia[nt].y);
            acc[mt][nt][0] = v0; acc[mt][nt][1] = v1;
            acc[mt][nt][2] = v2; acc[mt][nt][3] = v3;
            sA += v0 + v1; s2A += v0 * v0 + v1 * v1;
            sB += v2 + v3; s2B += v2 * v2 + v3 * v3;
        }
        #pragma unroll
        for (int o = 1; o <= 2; o <<= 1) {
            sA  += __shfl_xor_sync(0xFFFFFFFFu, sA,  o);
            s2A += __shfl_xor_sync(0xFFFFFFFFu, s2A, o);
            sB  += __shfl_xor_sync(0xFFFFFFFFu, sB,  o);
            s2B += __shfl_xor_sync(0xFFFFFFFFu, s2B, o);
        }
        if ((lane & 3) == 0) {
            int rA = wm * 32 + mt * 16 + (lane >> 2);
            ps[rA * 4 + wn]  = sA;  ps2[rA * 4 + wn]  = s2A;
            ps[(rA + 8) * 4 + wn] = sB; ps2[(rA + 8) * 4 + wn] = s2B;
        }
    }
    __syncthreads();

    #pragma unroll
    for (int mt = 0; mt < 2; mt++) {
        int rA = wm * 32 + mt * 16 + (lane >> 2);
        int rB = rA + 8;
        float tsA  = ps[rA * 4] + ps[rA * 4 + 1] + ps[rA * 4 + 2] + ps[rA * 4 + 3];
        float ts2A = ps2[rA * 4] + ps2[rA * 4 + 1] + ps2[rA * 4 + 2] + ps2[rA * 4 + 3];
        float tsB  = ps[rB * 4] + ps[rB * 4 + 1] + ps[rB * 4 + 2] + ps[rB * 4 + 3];
        float ts2B = ps2[rB * 4] + ps2[rB * 4 + 1] + ps2[rB * 4 + 2] + ps2[rB * 4 + 3];
        float muA = tsA * (1.f / 256.f);
        float muB = tsB * (1.f / 256.f);
        float invA = rsqrtf(ts2A * (1.f / 256.f) - muA * muA + 1e-5f);
        float invB = rsqrtf(ts2B * (1.f / 256.f) - muB * muB + 1e-5f);
        float mkA = mk[mt][0];
        float mkB = mk[mt][1];
        #pragma unroll
        for (int nt = 0; nt < 8; nt++) {
            int c = wn * 64 + nt * 8 + 2 * (lane & 3);
            float2 o1, o2;
            o1.x = ((acc[mt][nt][0] - muA) * invA * gg[nt].x + be[nt].x) * mkA;
            o1.y = ((acc[mt][nt][1] - muA) * invA * gg[nt].y + be[nt].y) * mkA;
            o2.x = ((acc[mt][nt][2] - muB) * invB * gg[nt].x + be[nt].x) * mkB;
            o2.y = ((acc[mt][nt][3] - muB) * invB * gg[nt].y + be[nt].y) * mkB;
            *(float2*)(out + (size_t)(m0 + rA) * DT + c) = o1;
            *(float2*)(out + (size_t)(m0 + rB) * DT + c) = o2;
        }
    }
}

// ---------------- launch ---------------------------------------------------
extern "C" void kernel_launch(void* const* d_in, const int* in_sizes, int n_in,
                              void* d_out, int out_size) {
    const float* student_emb = (const float*)d_in[0];
    const float* s_mask      = (const float*)d_in[1];
    const float* t_mask      = (const float*)d_in[2];
    int p = (in_sizes[3] == 64) ? 3 : 4;
    const float* pe_w1 = (const float*)d_in[p + 0];
    const float* pe_b1 = (const float*)d_in[p + 1];
    const float* pe_w2 = (const float*)d_in[p + 2];
    const float* pe_b2 = (const float*)d_in[p + 3];
    const float* pt_w  = (const float*)d_in[p + 4];
    const float* pt_b  = (const float*)d_in[p + 5];
    const float* ln_g  = (const float*)d_in[p + 6];
    const float* ln_b  = (const float*)d_in[p + 7];
    const float* nw    = (const float*)d_in[p + 8];
    float* out = (float*)d_out;

    cudaFuncSetAttribute(k_main, cudaFuncAttributeMaxDynamicSharedMemorySize, SMEM_TOTAL);

    k_prep_all<<<320, 256>>>(s_mask, nw, pt_w, pe_w1, pe_b1, pe_w2, pe_b2);
    k_main<<<NBLK, 256, SMEM_TOTAL>>>(student_emb, s_mask, t_mask,
                                      pt_b, ln_g, ln_b, out);
}